// round 3
// baseline (speedup 1.0000x reference)
#include <cuda_runtime.h>
#include <cstdint>

#define NB 16384
#define NE 256
#define NV 512
#define NT 16

__device__ float g_state[2][NB * NE];
__device__ float g_logits[NB * NV];
__device__ float g_G[512 * 768];
__device__ float g_WoutT[NE * NV];
__device__ int g_tok[NB];
__device__ int g_alive[NB];
__device__ int g_N[NB];
__device__ float g_logp[NB];
__device__ uint32_t g_keys[NT][2];

__device__ __forceinline__ uint32_t rotl32(uint32_t v, int r) {
    return (v << r) | (v >> (32 - r));
}
__device__ __forceinline__ void tfry(uint32_t k0, uint32_t k1,
                                     uint32_t c0, uint32_t c1,
                                     uint32_t& o0, uint32_t& o1) {
    uint32_t k2 = k0 ^ k1 ^ 0x1BD11BDAu;
    uint32_t x0 = c0 + k0, x1 = c1 + k1;
#define R4(a,b,c,d) { x0+=x1; x1=rotl32(x1,a); x1^=x0; x0+=x1; x1=rotl32(x1,b); x1^=x0; \
                      x0+=x1; x1=rotl32(x1,c); x1^=x0; x0+=x1; x1=rotl32(x1,d); x1^=x0; }
    R4(13,15,26,6)  x0 += k1; x1 += k2 + 1u;
    R4(17,29,16,24) x0 += k2; x1 += k0 + 2u;
    R4(13,15,26,6)  x0 += k0; x1 += k1 + 3u;
    R4(17,29,16,24) x0 += k1; x1 += k2 + 4u;
    R4(13,15,26,6)  x0 += k2; x1 += k0 + 5u;
#undef R4
    o0 = x0; o1 = x1;
}

__global__ void prep_kernel(const float* __restrict__ Wih,
                            const float* __restrict__ Whh,
                            const float* __restrict__ Wout) {
    int tid = blockIdx.x * blockDim.x + threadIdx.x;
    int stride = gridDim.x * blockDim.x;
    for (int i = tid; i < 512 * 768; i += stride) {
        int k = i / 768, c = i - k * 768;
        int j = c / 3, g = c - j * 3;
        int row = g * 256 + j;
        g_G[i] = (k < 256) ? Wih[row * 256 + k] : Whh[row * 256 + (k - 256)];
    }
    for (int i = tid; i < NE * NV; i += stride) {
        int k = i >> 9, v = i & 511;
        g_WoutT[i] = Wout[v * 256 + k];
    }
    if (blockIdx.x == 0 && threadIdx.x == 0) {
        // partitionable split: subkey t = threefry2x32((0,42), (0, t))
        for (int t = 0; t < NT; t++) {
            uint32_t a, b;
            tfry(0u, 42u, 0u, (uint32_t)t, a, b);
            g_keys[t][0] = a;
            g_keys[t][1] = b;
        }
    }
}

__global__ void init_kernel(const int* __restrict__ actions,
                            const float* __restrict__ h1) {
    int tid = blockIdx.x * blockDim.x + threadIdx.x;
    int stride = gridDim.x * blockDim.x;
    for (int i = tid; i < NB * NE; i += stride) {
        int b = i >> 8, e = i & 255;
        g_state[0][i] = h1[actions[b] * NE + e];
    }
    for (int i = tid; i < NB; i += stride) {
        g_tok[i] = 0; g_alive[i] = 1; g_N[i] = NT; g_logp[i] = 0.0f;
    }
}

// K1: gate GEMM (A=[emb|state] 512K x G 768) + GRU epilogue. 128 rows x 32 j.
__global__ __launch_bounds__(256, 2)
void k1_kernel(int cur,
               const float* __restrict__ d2e,
               const float* __restrict__ bih,
               const float* __restrict__ bhh) {
    const float* __restrict__ state_in = g_state[cur];
    float* __restrict__ state_out = g_state[cur ^ 1];
    __shared__ float As[128][32];
    __shared__ float Ws[32][96];
    int tid = threadIdx.x;
    int tx = tid & 31, ty = tid >> 5;
    int rowbase = blockIdx.y * 128;
    int j0 = blockIdx.x * 32;
    float accR[16], accZ[16], accA[16], accB[16];
#pragma unroll
    for (int i = 0; i < 16; i++) { accR[i] = accZ[i] = accA[i] = accB[i] = 0.0f; }
    int am = tid >> 3, akq = tid & 7;
    float4 aReg[4], wReg[3];

    auto loadChunk = [&](int ch) {
        int k0 = ch * 32;
        if (ch < 8) {
#pragma unroll
            for (int i = 0; i < 4; i++) {
                int row = rowbase + am + 32 * i;
                int tok = g_tok[row];
                aReg[i] = *(const float4*)&d2e[tok * NE + k0 + akq * 4];
            }
        } else {
#pragma unroll
            for (int i = 0; i < 4; i++) {
                int row = rowbase + am + 32 * i;
                aReg[i] = *(const float4*)&state_in[row * NE + (k0 - 256) + akq * 4];
            }
        }
#pragma unroll
        for (int i = 0; i < 3; i++) {
            int c = tid + 256 * i;
            int kk = c / 24, c4 = c - kk * 24;
            wReg[i] = *(const float4*)&g_G[(k0 + kk) * 768 + j0 * 3 + c4 * 4];
        }
    };
    auto storeChunk = [&]() {
#pragma unroll
        for (int i = 0; i < 4; i++)
            *(float4*)&As[am + 32 * i][akq * 4] = aReg[i];
#pragma unroll
        for (int i = 0; i < 3; i++) {
            int c = tid + 256 * i;
            int kk = c / 24, c4 = c - kk * 24;
            *(float4*)&Ws[kk][c4 * 4] = wReg[i];
        }
    };
    auto computeChunk = [&](float(&acc3)[16]) {
#pragma unroll
        for (int kk4 = 0; kk4 < 8; kk4++) {
            float w0[4], w1[4], w2[4];
#pragma unroll
            for (int i = 0; i < 4; i++) {
                int kk = kk4 * 4 + i;
                w0[i] = Ws[kk][tx * 3 + 0];
                w1[i] = Ws[kk][tx * 3 + 1];
                w2[i] = Ws[kk][tx * 3 + 2];
            }
#pragma unroll
            for (int rr = 0; rr < 16; rr++) {
                float4 a = *(const float4*)&As[ty * 16 + rr][kk4 * 4];
                accR[rr] += a.x * w0[0]; accR[rr] += a.y * w0[1];
                accR[rr] += a.z * w0[2]; accR[rr] += a.w * w0[3];
                accZ[rr] += a.x * w1[0]; accZ[rr] += a.y * w1[1];
                accZ[rr] += a.z * w1[2]; accZ[rr] += a.w * w1[3];
                acc3[rr] += a.x * w2[0]; acc3[rr] += a.y * w2[1];
                acc3[rr] += a.z * w2[2]; acc3[rr] += a.w * w2[3];
            }
        }
    };

    loadChunk(0); storeChunk();
    for (int ch = 0; ch < 16; ch++) {
        __syncthreads();
        if (ch < 15) loadChunk(ch + 1);
        if (ch < 8) computeChunk(accA); else computeChunk(accB);
        __syncthreads();
        if (ch < 15) storeChunk();
    }

    int j = j0 + tx;
    float br = bih[j] + bhh[j];
    float bz = bih[256 + j] + bhh[256 + j];
    float bin_ = bih[512 + j];
    float bhn = bhh[512 + j];
#pragma unroll
    for (int rr = 0; rr < 16; rr++) {
        int row = rowbase + ty * 16 + rr;
        float r = 1.0f / (1.0f + expf(-(accR[rr] + br)));
        float z = 1.0f / (1.0f + expf(-(accZ[rr] + bz)));
        float n = tanhf(accA[rr] + bin_ + r * (accB[rr] + bhn));
        float h = state_in[row * NE + j];
        state_out[row * NE + j] = (1.0f - z) * n + z * h;
    }
}

// K2: logits = state @ WoutT + b. 128 rows x 64 vocab.
__global__ __launch_bounds__(256, 2)
void k2_kernel(int nxt, const float* __restrict__ bout) {
    const float* __restrict__ st = g_state[nxt];
    __shared__ float As[128][32];
    __shared__ float Ws[32][64];
    int tid = threadIdx.x;
    int tx = tid & 31, ty = tid >> 5;
    int rowbase = blockIdx.y * 128;
    int v0 = blockIdx.x * 64;
    float acc0[16], acc1[16];
#pragma unroll
    for (int i = 0; i < 16; i++) { acc0[i] = acc1[i] = 0.0f; }
    int am = tid >> 3, akq = tid & 7;
    float4 aReg[4], wReg[2];

    auto loadChunk = [&](int ch) {
        int k0 = ch * 32;
#pragma unroll
        for (int i = 0; i < 4; i++) {
            int row = rowbase + am + 32 * i;
            aReg[i] = *(const float4*)&st[row * NE + k0 + akq * 4];
        }
#pragma unroll
        for (int i = 0; i < 2; i++) {
            int c = tid + 256 * i;
            int kk = c >> 4, c4 = c & 15;
            wReg[i] = *(const float4*)&g_WoutT[(k0 + kk) * NV + v0 + c4 * 4];
        }
    };
    auto storeChunk = [&]() {
#pragma unroll
        for (int i = 0; i < 4; i++)
            *(float4*)&As[am + 32 * i][akq * 4] = aReg[i];
#pragma unroll
        for (int i = 0; i < 2; i++) {
            int c = tid + 256 * i;
            int kk = c >> 4, c4 = c & 15;
            *(float4*)&Ws[kk][c4 * 4] = wReg[i];
        }
    };

    loadChunk(0); storeChunk();
    for (int ch = 0; ch < 8; ch++) {
        __syncthreads();
        if (ch < 7) loadChunk(ch + 1);
#pragma unroll
        for (int kk4 = 0; kk4 < 8; kk4++) {
            float wa[4], wb[4];
#pragma unroll
            for (int i = 0; i < 4; i++) {
                int kk = kk4 * 4 + i;
                wa[i] = Ws[kk][tx];
                wb[i] = Ws[kk][tx + 32];
            }
#pragma unroll
            for (int rr = 0; rr < 16; rr++) {
                float4 a = *(const float4*)&As[ty * 16 + rr][kk4 * 4];
                acc0[rr] += a.x * wa[0]; acc0[rr] += a.y * wa[1];
                acc0[rr] += a.z * wa[2]; acc0[rr] += a.w * wa[3];
                acc1[rr] += a.x * wb[0]; acc1[rr] += a.y * wb[1];
                acc1[rr] += a.z * wb[2]; acc1[rr] += a.w * wb[3];
            }
        }
        __syncthreads();
        if (ch < 7) storeChunk();
    }

    float b0 = bout[v0 + tx];
    float b1 = bout[v0 + tx + 32];
#pragma unroll
    for (int rr = 0; rr < 16; rr++) {
        int row = rowbase + ty * 16 + rr;
        g_logits[row * NV + v0 + tx] = acc0[rr] + b0;
        g_logits[row * NV + v0 + tx + 32] = acc1[rr] + b1;
    }
}

// K3: gumbel sample (JAX partitionable threefry: bits = o0^o1, counter (0,idx))
__global__ __launch_bounds__(256)
void k3_kernel(int t, float* __restrict__ out) {
    int gw = (blockIdx.x * blockDim.x + threadIdx.x) >> 5;
    int lane = threadIdx.x & 31;
    if (gw >= NB) return;
    uint32_t k0 = g_keys[t][0], k1 = g_keys[t][1];
    const float TINY = 1.17549435e-38f;

    float xv[16];
    float vb = -3.4e38f;
    int ib = 0;
    float m = -3.4e38f;
#pragma unroll
    for (int i = 0; i < 16; i++) {
        int v = lane + 32 * i;
        float x = g_logits[gw * NV + v];
        xv[i] = x;
        uint32_t idx = (uint32_t)(gw * NV + v);
        uint32_t o0, o1;
        tfry(k0, k1, 0u, idx, o0, o1);
        uint32_t bits = o0 ^ o1;
        float f = __uint_as_float((bits >> 9) | 0x3f800000u) - 1.0f;
        float u = fmaxf(TINY, f * (1.0f - TINY) + TINY);
        float g = -logf(-logf(u));
        float val = x + g;
        if (val > vb) { vb = val; ib = v; }
        m = fmaxf(m, x);
    }
#pragma unroll
    for (int off = 16; off > 0; off >>= 1) {
        float ov = __shfl_xor_sync(0xffffffffu, vb, off);
        int oi = __shfl_xor_sync(0xffffffffu, ib, off);
        float om = __shfl_xor_sync(0xffffffffu, m, off);
        if (ov > vb || (ov == vb && oi < ib)) { vb = ov; ib = oi; }
        m = fmaxf(m, om);
    }
    float s = 0.0f;
#pragma unroll
    for (int i = 0; i < 16; i++) s += expf(xv[i] - m);
#pragma unroll
    for (int off = 16; off > 0; off >>= 1)
        s += __shfl_xor_sync(0xffffffffu, s, off);

    if (lane == 0) {
        int tok = ib;
        float xt = g_logits[gw * NV + tok];
        float lp = (xt - m) - logf(s);
        int alive = g_alive[gw];
        if (alive) g_logp[gw] += lp;
        int tok_out = alive ? tok : 0;
        if (alive && tok == 0) g_N[gw] = t + 1;
        g_alive[gw] = (alive && tok != 0) ? 1 : 0;
        g_tok[gw] = tok_out;
        out[gw * NT + t] = (float)tok_out;
    }
}

__global__ void fin_kernel(float* __restrict__ out) {
    int b = blockIdx.x * blockDim.x + threadIdx.x;
    if (b < NB) {
        out[NB * NT + b] = (float)g_N[b];
        out[NB * NT + NB + b] = g_logp[b];
    }
}

extern "C" void kernel_launch(void* const* d_in, const int* in_sizes, int n_in,
                              void* d_out, int out_size) {
    const int* actions = (const int*)d_in[0];
    const float* h1 = (const float*)d_in[2];
    const float* d2e = (const float*)d_in[3];
    const float* Wih = (const float*)d_in[4];
    const float* Whh = (const float*)d_in[5];
    const float* bih = (const float*)d_in[6];
    const float* bhh = (const float*)d_in[7];
    const float* Wout = (const float*)d_in[8];
    const float* bout = (const float*)d_in[9];
    float* out = (float*)d_out;

    prep_kernel<<<1024, 256>>>(Wih, Whh, Wout);
    init_kernel<<<2048, 256>>>(actions, h1);
    for (int t = 0; t < NT; t++) {
        int cur = t & 1;
        k1_kernel<<<dim3(8, 128), 256>>>(cur, d2e, bih, bhh);
        k2_kernel<<<dim3(8, 128), 256>>>(cur ^ 1, bout);
        k3_kernel<<<2048, 256>>>(t, out);
    }
    fin_kernel<<<64, 256>>>(out);
}

// round 5
// speedup vs baseline: 1.6175x; 1.6175x over previous
#include <cuda_runtime.h>
#include <cuda_fp16.h>
#include <cstdint>

#define NB 16384
#define NE 256
#define NV 512
#define NT 16

// ---------------- scratch ----------------
__device__ __half g_st_h[2][NB * NE];
__device__ __half g_st_l[2][NB * NE];
__device__ __half g_GN_h[1024 * 512];
__device__ __half g_GN_l[1024 * 512];
__device__ __half g_emb_h[NV * NE];
__device__ __half g_emb_l[NV * NE];
__device__ __half g_Wo_h[NV * NE];
__device__ __half g_Wo_l[NV * NE];
__device__ float g_logits[NB * NV];
__device__ int g_tok[NB];
__device__ int g_alive[NB];
__device__ int g_N[NB];
__device__ float g_logp[NB];
__device__ uint32_t g_keys[NT][2];

// swizzled 16B-group byte offset within a [rows][32 fp16] tile
#define SWM(row, g) ((((row) * 4) + ((g) ^ ((((row) >> 1)) & 3))) * 16)

__device__ __forceinline__ uint32_t smem_u32(const void* p) {
    uint32_t a;
    asm("{ .reg .u64 t; cvta.to.shared.u64 t, %1; cvt.u32.u64 %0, t; }" : "=r"(a) : "l"(p));
    return a;
}
__device__ __forceinline__ void cpa16(uint32_t s, const void* g) {
    asm volatile("cp.async.ca.shared.global [%0], [%1], 16;" :: "r"(s), "l"(g));
}
__device__ __forceinline__ void ldm4(uint32_t* r, uint32_t a) {
    asm volatile("ldmatrix.sync.aligned.m8n8.x4.shared.b16 {%0,%1,%2,%3}, [%4];"
                 : "=r"(r[0]), "=r"(r[1]), "=r"(r[2]), "=r"(r[3]) : "r"(a));
}
__device__ __forceinline__ void ldm2(uint32_t* r, uint32_t a) {
    asm volatile("ldmatrix.sync.aligned.m8n8.x2.shared.b16 {%0,%1}, [%2];"
                 : "=r"(r[0]), "=r"(r[1]) : "r"(a));
}
__device__ __forceinline__ void mma16816(float* c, const uint32_t* a, const uint32_t* b) {
    asm volatile(
        "mma.sync.aligned.m16n8k16.row.col.f32.f16.f16.f32 "
        "{%0,%1,%2,%3}, {%4,%5,%6,%7}, {%8,%9}, {%0,%1,%2,%3};"
        : "+f"(c[0]), "+f"(c[1]), "+f"(c[2]), "+f"(c[3])
        : "r"(a[0]), "r"(a[1]), "r"(a[2]), "r"(a[3]), "r"(b[0]), "r"(b[1]));
}
__device__ __forceinline__ void split2(float v, __half& h, __half& l) {
    h = __float2half(v);
    l = __float2half(v - __half2float(h));
}

// ---------------- threefry ----------------
__device__ __forceinline__ uint32_t rotl32(uint32_t v, int r) {
    return (v << r) | (v >> (32 - r));
}
__device__ __forceinline__ void tfry(uint32_t k0, uint32_t k1,
                                     uint32_t c0, uint32_t c1,
                                     uint32_t& o0, uint32_t& o1) {
    uint32_t k2 = k0 ^ k1 ^ 0x1BD11BDAu;
    uint32_t x0 = c0 + k0, x1 = c1 + k1;
#define R4(a,b,c,d) { x0+=x1; x1=rotl32(x1,a); x1^=x0; x0+=x1; x1=rotl32(x1,b); x1^=x0; \
                      x0+=x1; x1=rotl32(x1,c); x1^=x0; x0+=x1; x1=rotl32(x1,d); x1^=x0; }
    R4(13,15,26,6)  x0 += k1; x1 += k2 + 1u;
    R4(17,29,16,24) x0 += k2; x1 += k0 + 2u;
    R4(13,15,26,6)  x0 += k0; x1 += k1 + 3u;
    R4(17,29,16,24) x0 += k1; x1 += k2 + 4u;
    R4(13,15,26,6)  x0 += k2; x1 += k0 + 5u;
#undef R4
    o0 = x0; o1 = x1;
}

// ---------------- prep ----------------
__global__ void prep_kernel(const float* __restrict__ Wih,
                            const float* __restrict__ Whh,
                            const float* __restrict__ Wout,
                            const float* __restrict__ d2e) {
    int tid = blockIdx.x * blockDim.x + threadIdx.x;
    int stride = gridDim.x * blockDim.x;
    // GN[gate*256+j][k]; i_n valid only k<256, h_n only k>=256 (zero-masked)
    for (int i = tid; i < 1024 * 512; i += stride) {
        int np = i >> 9, k = i & 511;
        int g = np >> 8, j = np & 255;
        float v;
        if (g == 0)      v = (k < 256) ? Wih[j * 256 + k] : Whh[j * 256 + k - 256];
        else if (g == 1) v = (k < 256) ? Wih[(256 + j) * 256 + k] : Whh[(256 + j) * 256 + k - 256];
        else if (g == 2) v = (k < 256) ? Wih[(512 + j) * 256 + k] : 0.0f;
        else             v = (k < 256) ? 0.0f : Whh[(512 + j) * 256 + k - 256];
        __half h, l; split2(v, h, l);
        g_GN_h[i] = h; g_GN_l[i] = l;
    }
    for (int i = tid; i < NV * NE; i += stride) {
        __half h, l;
        split2(Wout[i], h, l);
        g_Wo_h[i] = h; g_Wo_l[i] = l;
        split2(d2e[i], h, l);
        g_emb_h[i] = h; g_emb_l[i] = l;
    }
    if (blockIdx.x == 0 && threadIdx.x == 0) {
        for (int t = 0; t < NT; t++) {
            uint32_t a, b;
            tfry(0u, 42u, 0u, (uint32_t)t, a, b);
            g_keys[t][0] = a; g_keys[t][1] = b;
        }
    }
}

__global__ void init_kernel(const int* __restrict__ actions,
                            const float* __restrict__ h1) {
    int tid = blockIdx.x * blockDim.x + threadIdx.x;
    int stride = gridDim.x * blockDim.x;
    for (int i = tid; i < NB * NE; i += stride) {
        int b = i >> 8, e = i & 255;
        float v = h1[actions[b] * NE + e];
        __half h, l; split2(v, h, l);
        g_st_h[0][i] = h; g_st_l[0][i] = l;
    }
    for (int i = tid; i < NB; i += stride) {
        g_tok[i] = 0; g_alive[i] = 1; g_N[i] = NT; g_logp[i] = 0.0f;
    }
}

// ============ K1: gate GEMM (fp16 split mma) + GRU epilogue ============
// grid (8 jblk, 128 rowblk), 256 thr. C tile 128 rows x 128 n (4 gates x 32 j).
// smem: [buf][Ah 8K | Al 8K | Bh 8K | Bl 8K] x2 = 64KB; epilogue Cs fp32 128x132.
#define K1_SMEM (128 * 132 * 4)
__global__ __launch_bounds__(256)
void k1_mma(int cur, const float* __restrict__ bih, const float* __restrict__ bhh) {
    extern __shared__ char smem[];
    const uint32_t sbase = smem_u32(smem);
    const int tid = threadIdx.x;
    const int lane = tid & 31, wid = tid >> 5;
    const int wm = wid & 1, wn = wid >> 1;
    const int j0 = blockIdx.x * 32;
    const int rbase = blockIdx.y * 128;
    const int nxt = cur ^ 1;

    const int arow = tid >> 1, ahalf = tid & 1;
    const int tokr = g_tok[rbase + arow];
    const int gnrow = (arow >> 5) * 256 + j0 + (arow & 31);
    const uint32_t sw0 = SWM(arow, ahalf * 2);
    const uint32_t sw1 = SWM(arow, ahalf * 2 + 1);

    float acc[4][4][4];
#pragma unroll
    for (int i = 0; i < 4; i++)
#pragma unroll
        for (int j = 0; j < 4; j++)
#pragma unroll
            for (int q = 0; q < 4; q++) acc[i][j][q] = 0.0f;

    auto stage = [&](int c, int buf) {
        uint32_t ab = sbase + buf * 32768;
        const __half *a0, *a1;
        if (c < 8) {
            size_t off = (size_t)tokr * 256 + c * 32 + ahalf * 16;
            a0 = g_emb_h + off; a1 = g_emb_l + off;
        } else {
            size_t off = (size_t)(rbase + arow) * 256 + (c - 8) * 32 + ahalf * 16;
            a0 = g_st_h[cur] + off; a1 = g_st_l[cur] + off;
        }
        cpa16(ab + sw0, a0);            cpa16(ab + sw1, a0 + 8);
        cpa16(ab + 8192 + sw0, a1);     cpa16(ab + 8192 + sw1, a1 + 8);
        size_t offb = (size_t)gnrow * 512 + c * 32 + ahalf * 16;
        cpa16(ab + 16384 + sw0, g_GN_h + offb);
        cpa16(ab + 16384 + sw1, g_GN_h + offb + 8);
        cpa16(ab + 24576 + sw0, g_GN_l + offb);
        cpa16(ab + 24576 + sw1, g_GN_l + offb + 8);
    };

    stage(0, 0);
    asm volatile("cp.async.commit_group;");
    for (int c = 0; c < 16; c++) {
        if (c < 15) {
            stage(c + 1, (c + 1) & 1);
            asm volatile("cp.async.commit_group;");
            asm volatile("cp.async.wait_group 1;");
        } else {
            asm volatile("cp.async.wait_group 0;");
        }
        __syncthreads();
        uint32_t ab = sbase + (c & 1) * 32768;
#pragma unroll
        for (int q = 0; q < 2; q++) {
            int gb = q * 2;
            uint32_t aAddr[4], bAddr[4];
            {
                int rl = wm * 64 + (lane & 15);
                int ga = gb + (lane >> 4);
#pragma unroll
                for (int mt = 0; mt < 4; mt++) {
                    int row = rl + mt * 16;
                    aAddr[mt] = ab + SWM(row, ga);
                }
                int rb = wn * 32 + (lane & 7);
                int gbb = gb + ((lane >> 3) & 1);
#pragma unroll
                for (int nt = 0; nt < 4; nt++) {
                    int row = rb + nt * 8;
                    bAddr[nt] = ab + 16384 + SWM(row, gbb);
                }
            }
            uint32_t af[4][4], bh[4][2], bl[4][2];
#pragma unroll
            for (int mt = 0; mt < 4; mt++) ldm4(af[mt], aAddr[mt]);
#pragma unroll
            for (int nt = 0; nt < 4; nt++) ldm2(bh[nt], bAddr[nt]);
#pragma unroll
            for (int mt = 0; mt < 4; mt++)
#pragma unroll
                for (int nt = 0; nt < 4; nt++) mma16816(acc[mt][nt], af[mt], bh[nt]);
#pragma unroll
            for (int nt = 0; nt < 4; nt++) ldm2(bl[nt], bAddr[nt] + 8192);
#pragma unroll
            for (int mt = 0; mt < 4; mt++)
#pragma unroll
                for (int nt = 0; nt < 4; nt++) mma16816(acc[mt][nt], af[mt], bl[nt]);
#pragma unroll
            for (int mt = 0; mt < 4; mt++) ldm4(af[mt], aAddr[mt] + 8192);
#pragma unroll
            for (int mt = 0; mt < 4; mt++)
#pragma unroll
                for (int nt = 0; nt < 4; nt++) mma16816(acc[mt][nt], af[mt], bh[nt]);
        }
        __syncthreads();
    }

    // ---- epilogue: exchange gates via smem, GRU, split-store state ----
    float* Cs = (float*)smem;
#pragma unroll
    for (int mt = 0; mt < 4; mt++)
#pragma unroll
        for (int nt = 0; nt < 4; nt++) {
            int r0 = wm * 64 + mt * 16 + (lane >> 2);
            int c0 = wn * 32 + nt * 8 + (lane & 3) * 2;
            Cs[r0 * 132 + c0] = acc[mt][nt][0];
            Cs[r0 * 132 + c0 + 1] = acc[mt][nt][1];
            Cs[(r0 + 8) * 132 + c0] = acc[mt][nt][2];
            Cs[(r0 + 8) * 132 + c0 + 1] = acc[mt][nt][3];
        }
    __syncthreads();

    {
        int jl = tid & 31, rseg = tid >> 5;
        int j = j0 + jl;
        float br = bih[j] + bhh[j];
        float bz = bih[256 + j] + bhh[256 + j];
        float bi = bih[512 + j];
        float bhn = bhh[512 + j];
#pragma unroll
        for (int rr = 0; rr < 16; rr++) {
            int r = rseg * 16 + rr;
            int grow = rbase + r;
            float cr = Cs[r * 132 + jl];
            float cz = Cs[r * 132 + 32 + jl];
            float ci = Cs[r * 132 + 64 + jl];
            float ch = Cs[r * 132 + 96 + jl];
            size_t so = (size_t)grow * 256 + j;
            float hold = __half2float(g_st_h[cur][so]) + __half2float(g_st_l[cur][so]);
            float rg = 1.0f / (1.0f + expf(-(cr + br)));
            float zg = 1.0f / (1.0f + expf(-(cz + bz)));
            float nn = tanhf(ci + bi + rg * (ch + bhn));
            float v = (1.0f - zg) * nn + zg * hold;
            __half hh, hl;
            split2(v, hh, hl);
            g_st_h[nxt][so] = hh;
            g_st_l[nxt][so] = hl;
        }
    }
}

// ============ K2: logits GEMM (fp16 split mma) ============
// grid (4 vblk, 128 rowblk), 256 thr. C tile 128 x 128 v. K = 256.
#define K2_SMEM 65536
__global__ __launch_bounds__(256)
void k2_mma(int nxt, const float* __restrict__ bout) {
    extern __shared__ char smem[];
    const uint32_t sbase = smem_u32(smem);
    const int tid = threadIdx.x;
    const int lane = tid & 31, wid = tid >> 5;
    const int wm = wid & 1, wn = wid >> 1;
    const int v0 = blockIdx.x * 128;
    const int rbase = blockIdx.y * 128;

    const int arow = tid >> 1, ahalf = tid & 1;
    const uint32_t sw0 = SWM(arow, ahalf * 2);
    const uint32_t sw1 = SWM(arow, ahalf * 2 + 1);

    float acc[4][4][4];
#pragma unroll
    for (int i = 0; i < 4; i++)
#pragma unroll
        for (int j = 0; j < 4; j++)
#pragma unroll
            for (int q = 0; q < 4; q++) acc[i][j][q] = 0.0f;

    auto stage = [&](int c, int buf) {
        uint32_t ab = sbase + buf * 32768;
        size_t off = (size_t)(rbase + arow) * 256 + c * 32 + ahalf * 16;
        cpa16(ab + sw0, g_st_h[nxt] + off);
        cpa16(ab + sw1, g_st_h[nxt] + off + 8);
        cpa16(ab + 8192 + sw0, g_st_l[nxt] + off);
        cpa16(ab + 8192 + sw1, g_st_l[nxt] + off + 8);
        size_t offb = (size_t)(v0 + arow) * 256 + c * 32 + ahalf * 16;
        cpa16(ab + 16384 + sw0, g_Wo_h + offb);
        cpa16(ab + 16384 + sw1, g_Wo_h + offb + 8);
        cpa16(ab + 24576 + sw0, g_Wo_l + offb);
        cpa16(ab + 24576 + sw1, g_Wo_l + offb + 8);
    };

    stage(0, 0);
    asm volatile("cp.async.commit_group;");
    for (int c = 0; c < 8; c++) {
        if (c < 7) {
            stage(c + 1, (c + 1) & 1);
            asm volatile("cp.async.commit_group;");
            asm volatile("cp.async.wait_group 1;");
        } else {
            asm volatile("cp.async.wait_group 0;");
        }
        __syncthreads();
        uint32_t ab = sbase + (c & 1) * 32768;
#pragma unroll
        for (int q = 0; q < 2; q++) {
            int gb = q * 2;
            uint32_t aAddr[4], bAddr[4];
            {
                int rl = wm * 64 + (lane & 15);
                int ga = gb + (lane >> 4);
#pragma unroll
                for (int mt = 0; mt < 4; mt++) {
                    int row = rl + mt * 16;
                    aAddr[mt] = ab + SWM(row, ga);
                }
                int rb = wn * 32 + (lane & 7);
                int gbb = gb + ((lane >> 3) & 1);
#pragma unroll
                for (int nt = 0; nt < 4; nt++) {
                    int row = rb + nt * 8;
                    bAddr[nt] = ab + 16384 + SWM(row, gbb);
                }
            }
            uint32_t af[4][4], bh[4][2], bl[4][2];
#pragma unroll
            for (int mt = 0; mt < 4; mt++) ldm4(af[mt], aAddr[mt]);
#pragma unroll
            for (int nt = 0; nt < 4; nt++) ldm2(bh[nt], bAddr[nt]);
#pragma unroll
            for (int mt = 0; mt < 4; mt++)
#pragma unroll
                for (int nt = 0; nt < 4; nt++) mma16816(acc[mt][nt], af[mt], bh[nt]);
#pragma unroll
            for (int nt = 0; nt < 4; nt++) ldm2(bl[nt], bAddr[nt] + 8192);
#pragma unroll
            for (int mt = 0; mt < 4; mt++)
#pragma unroll
                for (int nt = 0; nt < 4; nt++) mma16816(acc[mt][nt], af[mt], bl[nt]);
#pragma unroll
            for (int mt = 0; mt < 4; mt++) ldm4(af[mt], aAddr[mt] + 8192);
#pragma unroll
            for (int mt = 0; mt < 4; mt++)
#pragma unroll
                for (int nt = 0; nt < 4; nt++) mma16816(acc[mt][nt], af[mt], bh[nt]);
        }
        __syncthreads();
    }

    // direct store with bias
#pragma unroll
    for (int nt = 0; nt < 4; nt++) {
        int c0 = v0 + wn * 32 + nt * 8 + (lane & 3) * 2;
        float b0 = bout[c0], b1 = bout[c0 + 1];
#pragma unroll
        for (int mt = 0; mt < 4; mt++) {
            int r0 = rbase + wm * 64 + mt * 16 + (lane >> 2);
            float2 s0 = make_float2(acc[mt][nt][0] + b0, acc[mt][nt][1] + b1);
            float2 s1 = make_float2(acc[mt][nt][2] + b0, acc[mt][nt][3] + b1);
            *(float2*)&g_logits[(size_t)r0 * NV + c0] = s0;
            *(float2*)&g_logits[(size_t)(r0 + 8) * NV + c0] = s1;
        }
    }
}

// ---------------- K3: gumbel sample + bookkeeping (proven bit-exact) ----------------
__global__ __launch_bounds__(256)
void k3_kernel(int t, float* __restrict__ out) {
    int gw = (blockIdx.x * blockDim.x + threadIdx.x) >> 5;
    int lane = threadIdx.x & 31;
    if (gw >= NB) return;
    uint32_t k0 = g_keys[t][0], k1 = g_keys[t][1];
    const float TINY = 1.17549435e-38f;

    float xv[16];
    float vb = -3.4e38f;
    int ib = 0;
    float m = -3.4e38f;
#pragma unroll
    for (int i = 0; i < 16; i++) {
        int v = lane + 32 * i;
        float x = g_logits[gw * NV + v];
        xv[i] = x;
        uint32_t idx = (uint32_t)(gw * NV + v);
        uint32_t o0, o1;
        tfry(k0, k1, 0u, idx, o0, o1);
        uint32_t bits = o0 ^ o1;
        float f = __uint_as_float((bits >> 9) | 0x3f800000u) - 1.0f;
        float u = fmaxf(TINY, f * (1.0f - TINY) + TINY);
        float g = -logf(-logf(u));
        float val = x + g;
        if (val > vb) { vb = val; ib = v; }
        m = fmaxf(m, x);
    }
#pragma unroll
    for (int off = 16; off > 0; off >>= 1) {
        float ov = __shfl_xor_sync(0xffffffffu, vb, off);
        int oi = __shfl_xor_sync(0xffffffffu, ib, off);
        float om = __shfl_xor_sync(0xffffffffu, m, off);
        if (ov > vb || (ov == vb && oi < ib)) { vb = ov; ib = oi; }
        m = fmaxf(m, om);
    }
    float s = 0.0f;
#pragma unroll
    for (int i = 0; i < 16; i++) s += expf(xv[i] - m);
#pragma unroll
    for (int off = 16; off > 0; off >>= 1)
        s += __shfl_xor_sync(0xffffffffu, s, off);

    if (lane == 0) {
        int tok = ib;
        float xt = g_logits[gw * NV + tok];
        float lp = (xt - m) - logf(s);
        int alive = g_alive[gw];
        if (alive) g_logp[gw] += lp;
        int tok_out = alive ? tok : 0;
        if (alive && tok == 0) g_N[gw] = t + 1;
        g_alive[gw] = (alive && tok != 0) ? 1 : 0;
        g_tok[gw] = tok_out;
        out[gw * NT + t] = (float)tok_out;
    }
}

__global__ void fin_kernel(float* __restrict__ out) {
    int b = blockIdx.x * blockDim.x + threadIdx.x;
    if (b < NB) {
        out[NB * NT + b] = (float)g_N[b];
        out[NB * NT + NB + b] = g_logp[b];
    }
}

extern "C" void kernel_launch(void* const* d_in, const int* in_sizes, int n_in,
                              void* d_out, int out_size) {
    const int* actions = (const int*)d_in[0];
    const float* h1 = (const float*)d_in[2];
    const float* d2e = (const float*)d_in[3];
    const float* Wih = (const float*)d_in[4];
    const float* Whh = (const float*)d_in[5];
    const float* bih = (const float*)d_in[6];
    const float* bhh = (const float*)d_in[7];
    const float* Wout = (const float*)d_in[8];
    const float* bout = (const float*)d_in[9];
    float* out = (float*)d_out;

    cudaFuncSetAttribute(k1_mma, cudaFuncAttributeMaxDynamicSharedMemorySize, K1_SMEM);
    cudaFuncSetAttribute(k2_mma, cudaFuncAttributeMaxDynamicSharedMemorySize, K2_SMEM);

    prep_kernel<<<1024, 256>>>(Wih, Whh, Wout, d2e);
    init_kernel<<<2048, 256>>>(actions, h1);
    for (int t = 0; t < NT; t++) {
        int cur = t & 1;
        k1_mma<<<dim3(8, 128), 256, K1_SMEM>>>(cur, bih, bhh);
        k2_mma<<<dim3(4, 128), 256, K2_SMEM>>>(cur ^ 1, bout);
        k3_kernel<<<2048, 256>>>(t, out);
    }
    fin_kernel<<<64, 256>>>(out);
}

// round 6
// speedup vs baseline: 1.7960x; 1.1103x over previous
#include <cuda_runtime.h>
#include <cuda_fp16.h>
#include <cstdint>

#define NB 16384
#define NE 256
#define NV 512
#define NT 16

// ---------------- scratch ----------------
__device__ __half g_st_h[2][NB * NE];
__device__ __half g_st_l[2][NB * NE];
__device__ __half g_GN_h[1024 * 512];
__device__ __half g_GN_l[1024 * 512];
__device__ __half g_emb_h[NV * NE];
__device__ __half g_emb_l[NV * NE];
__device__ __half g_Wo_h[NV * NE];
__device__ __half g_Wo_l[NV * NE];
__device__ float g_logits[NB * NV];
__device__ int g_tok[NB];
__device__ int g_alive[NB];
__device__ int g_N[NB];
__device__ float g_logp[NB];
__device__ uint32_t g_keys[NT][2];

// swizzled 16B-group byte offset within a [rows][32 fp16] tile
#define SWM(row, g) ((((row) * 4) + ((g) ^ ((((row) >> 1)) & 3))) * 16)

__device__ __forceinline__ uint32_t smem_u32(const void* p) {
    uint32_t a;
    asm("{ .reg .u64 t; cvta.to.shared.u64 t, %1; cvt.u32.u64 %0, t; }" : "=r"(a) : "l"(p));
    return a;
}
__device__ __forceinline__ void cpa16(uint32_t s, const void* g) {
    asm volatile("cp.async.ca.shared.global [%0], [%1], 16;" :: "r"(s), "l"(g));
}
__device__ __forceinline__ void ldm4(uint32_t* r, uint32_t a) {
    asm volatile("ldmatrix.sync.aligned.m8n8.x4.shared.b16 {%0,%1,%2,%3}, [%4];"
                 : "=r"(r[0]), "=r"(r[1]), "=r"(r[2]), "=r"(r[3]) : "r"(a));
}
__device__ __forceinline__ void ldm2(uint32_t* r, uint32_t a) {
    asm volatile("ldmatrix.sync.aligned.m8n8.x2.shared.b16 {%0,%1}, [%2];"
                 : "=r"(r[0]), "=r"(r[1]) : "r"(a));
}
__device__ __forceinline__ void mma16816(float* c, const uint32_t* a, const uint32_t* b) {
    asm volatile(
        "mma.sync.aligned.m16n8k16.row.col.f32.f16.f16.f32 "
        "{%0,%1,%2,%3}, {%4,%5,%6,%7}, {%8,%9}, {%0,%1,%2,%3};"
        : "+f"(c[0]), "+f"(c[1]), "+f"(c[2]), "+f"(c[3])
        : "r"(a[0]), "r"(a[1]), "r"(a[2]), "r"(a[3]), "r"(b[0]), "r"(b[1]));
}
__device__ __forceinline__ void split2(float v, __half& h, __half& l) {
    h = __float2half(v);
    l = __float2half(v - __half2float(h));
}

// ---------------- threefry ----------------
__device__ __forceinline__ uint32_t rotl32(uint32_t v, int r) {
    return (v << r) | (v >> (32 - r));
}
__device__ __forceinline__ void tfry(uint32_t k0, uint32_t k1,
                                     uint32_t c0, uint32_t c1,
                                     uint32_t& o0, uint32_t& o1) {
    uint32_t k2 = k0 ^ k1 ^ 0x1BD11BDAu;
    uint32_t x0 = c0 + k0, x1 = c1 + k1;
#define R4(a,b,c,d) { x0+=x1; x1=rotl32(x1,a); x1^=x0; x0+=x1; x1=rotl32(x1,b); x1^=x0; \
                      x0+=x1; x1=rotl32(x1,c); x1^=x0; x0+=x1; x1=rotl32(x1,d); x1^=x0; }
    R4(13,15,26,6)  x0 += k1; x1 += k2 + 1u;
    R4(17,29,16,24) x0 += k2; x1 += k0 + 2u;
    R4(13,15,26,6)  x0 += k0; x1 += k1 + 3u;
    R4(17,29,16,24) x0 += k1; x1 += k2 + 4u;
    R4(13,15,26,6)  x0 += k2; x1 += k0 + 5u;
#undef R4
    o0 = x0; o1 = x1;
}

// ---------------- prep ----------------
__global__ void prep_kernel(const float* __restrict__ Wih,
                            const float* __restrict__ Whh,
                            const float* __restrict__ Wout,
                            const float* __restrict__ d2e) {
    int tid = blockIdx.x * blockDim.x + threadIdx.x;
    int stride = gridDim.x * blockDim.x;
    for (int i = tid; i < 1024 * 512; i += stride) {
        int np = i >> 9, k = i & 511;
        int g = np >> 8, j = np & 255;
        float v;
        if (g == 0)      v = (k < 256) ? Wih[j * 256 + k] : Whh[j * 256 + k - 256];
        else if (g == 1) v = (k < 256) ? Wih[(256 + j) * 256 + k] : Whh[(256 + j) * 256 + k - 256];
        else if (g == 2) v = (k < 256) ? Wih[(512 + j) * 256 + k] : 0.0f;
        else             v = (k < 256) ? 0.0f : Whh[(512 + j) * 256 + k - 256];
        __half h, l; split2(v, h, l);
        g_GN_h[i] = h; g_GN_l[i] = l;
    }
    for (int i = tid; i < NV * NE; i += stride) {
        __half h, l;
        split2(Wout[i], h, l);
        g_Wo_h[i] = h; g_Wo_l[i] = l;
        split2(d2e[i], h, l);
        g_emb_h[i] = h; g_emb_l[i] = l;
    }
    if (blockIdx.x == 0 && threadIdx.x == 0) {
        for (int t = 0; t < NT; t++) {
            uint32_t a, b;
            tfry(0u, 42u, 0u, (uint32_t)t, a, b);
            g_keys[t][0] = a; g_keys[t][1] = b;
        }
    }
}

__global__ void init_kernel(const int* __restrict__ actions,
                            const float* __restrict__ h1) {
    int tid = blockIdx.x * blockDim.x + threadIdx.x;
    int stride = gridDim.x * blockDim.x;
    for (int i = tid; i < NB * NE; i += stride) {
        int b = i >> 8, e = i & 255;
        float v = h1[actions[b] * NE + e];
        __half h, l; split2(v, h, l);
        g_st_h[0][i] = h; g_st_l[0][i] = l;
    }
    for (int i = tid; i < NB; i += stride) {
        g_tok[i] = 0; g_alive[i] = 1; g_N[i] = NT; g_logp[i] = 0.0f;
    }
}

// ============ K1: gate GEMM (fp16 split mma) + GRU epilogue ============
// grid (8 jblk, 128 rowblk), 256 thr. C tile 128 rows x 128 n (4 gates x 32 j).
// 3-stage cp.async pipeline, 32KB/stage; epilogue in two 64-row phases (Cs 33.8KB).
#define K1_SMEM (3 * 32768)
__global__ __launch_bounds__(256, 2)
void k1_mma(int cur, const float* __restrict__ bih, const float* __restrict__ bhh) {
    extern __shared__ char smem[];
    const uint32_t sbase = smem_u32(smem);
    const int tid = threadIdx.x;
    const int lane = tid & 31, wid = tid >> 5;
    const int wm = wid & 1, wn = wid >> 1;
    const int j0 = blockIdx.x * 32;
    const int rbase = blockIdx.y * 128;
    const int nxt = cur ^ 1;

    const int arow = tid >> 1, ahalf = tid & 1;
    const int tokr = g_tok[rbase + arow];
    const int gnrow = (arow >> 5) * 256 + j0 + (arow & 31);
    const uint32_t sw0 = SWM(arow, ahalf * 2);
    const uint32_t sw1 = SWM(arow, ahalf * 2 + 1);

    float acc[4][4][4];
#pragma unroll
    for (int i = 0; i < 4; i++)
#pragma unroll
        for (int j = 0; j < 4; j++)
#pragma unroll
            for (int q = 0; q < 4; q++) acc[i][j][q] = 0.0f;

    auto stage = [&](int c, int buf) {
        uint32_t ab = sbase + buf * 32768;
        const __half *a0, *a1;
        if (c < 8) {
            size_t off = (size_t)tokr * 256 + c * 32 + ahalf * 16;
            a0 = g_emb_h + off; a1 = g_emb_l + off;
        } else {
            size_t off = (size_t)(rbase + arow) * 256 + (c - 8) * 32 + ahalf * 16;
            a0 = g_st_h[cur] + off; a1 = g_st_l[cur] + off;
        }
        cpa16(ab + sw0, a0);            cpa16(ab + sw1, a0 + 8);
        cpa16(ab + 8192 + sw0, a1);     cpa16(ab + 8192 + sw1, a1 + 8);
        size_t offb = (size_t)gnrow * 512 + c * 32 + ahalf * 16;
        cpa16(ab + 16384 + sw0, g_GN_h + offb);
        cpa16(ab + 16384 + sw1, g_GN_h + offb + 8);
        cpa16(ab + 24576 + sw0, g_GN_l + offb);
        cpa16(ab + 24576 + sw1, g_GN_l + offb + 8);
    };

    stage(0, 0);
    asm volatile("cp.async.commit_group;");
    stage(1, 1);
    asm volatile("cp.async.commit_group;");

    for (int c = 0; c < 16; c++) {
        if (c < 15) asm volatile("cp.async.wait_group 1;");
        else        asm volatile("cp.async.wait_group 0;");
        __syncthreads();
        if (c < 14) {
            stage(c + 2, (c + 2) % 3);
            asm volatile("cp.async.commit_group;");
        }
        // gate-skip: wn==2 is i_n (k<256 only), wn==3 is h_n (k>=256 only)
        if ((wn == 2 && c >= 8) || (wn == 3 && c < 8)) continue;
        uint32_t ab = sbase + (c % 3) * 32768;
#pragma unroll
        for (int q = 0; q < 2; q++) {
            int gb = q * 2;
            uint32_t aAddr[4], bAddr[4];
            {
                int rl = wm * 64 + (lane & 15);
                int ga = gb + (lane >> 4);
#pragma unroll
                for (int mt = 0; mt < 4; mt++) {
                    int row = rl + mt * 16;
                    aAddr[mt] = ab + SWM(row, ga);
                }
                int rb = wn * 32 + (lane & 7);
                int gbb = gb + ((lane >> 3) & 1);
#pragma unroll
                for (int nt = 0; nt < 4; nt++) {
                    int row = rb + nt * 8;
                    bAddr[nt] = ab + 16384 + SWM(row, gbb);
                }
            }
            uint32_t af[4][4], bh[4][2], bl[4][2];
#pragma unroll
            for (int mt = 0; mt < 4; mt++) ldm4(af[mt], aAddr[mt]);
#pragma unroll
            for (int nt = 0; nt < 4; nt++) ldm2(bh[nt], bAddr[nt]);
#pragma unroll
            for (int mt = 0; mt < 4; mt++)
#pragma unroll
                for (int nt = 0; nt < 4; nt++) mma16816(acc[mt][nt], af[mt], bh[nt]);
#pragma unroll
            for (int nt = 0; nt < 4; nt++) ldm2(bl[nt], bAddr[nt] + 8192);
#pragma unroll
            for (int mt = 0; mt < 4; mt++)
#pragma unroll
                for (int nt = 0; nt < 4; nt++) mma16816(acc[mt][nt], af[mt], bl[nt]);
#pragma unroll
            for (int mt = 0; mt < 4; mt++) ldm4(af[mt], aAddr[mt] + 8192);
#pragma unroll
            for (int mt = 0; mt < 4; mt++)
#pragma unroll
                for (int nt = 0; nt < 4; nt++) mma16816(acc[mt][nt], af[mt], bh[nt]);
        }
    }

    // ---- epilogue: two 64-row phases; Cs[64][132] reuses stage smem ----
    float* Cs = (float*)smem;
#pragma unroll
    for (int ph = 0; ph < 2; ph++) {
        __syncthreads();
        if (wm == ph) {
#pragma unroll
            for (int mt = 0; mt < 4; mt++)
#pragma unroll
                for (int nt = 0; nt < 4; nt++) {
                    int r0 = mt * 16 + (lane >> 2);
                    int c0 = wn * 32 + nt * 8 + (lane & 3) * 2;
                    Cs[r0 * 132 + c0] = acc[mt][nt][0];
                    Cs[r0 * 132 + c0 + 1] = acc[mt][nt][1];
                    Cs[(r0 + 8) * 132 + c0] = acc[mt][nt][2];
                    Cs[(r0 + 8) * 132 + c0 + 1] = acc[mt][nt][3];
                }
        }
        __syncthreads();
        {
            int jl = tid & 31, rseg = tid >> 5;
            int j = j0 + jl;
            float br = bih[j] + bhh[j];
            float bz = bih[256 + j] + bhh[256 + j];
            float bi = bih[512 + j];
            float bhn = bhh[512 + j];
#pragma unroll
            for (int rr = 0; rr < 8; rr++) {
                int r = rseg * 8 + rr;
                int grow = rbase + ph * 64 + r;
                float cr = Cs[r * 132 + jl];
                float cz = Cs[r * 132 + 32 + jl];
                float ci = Cs[r * 132 + 64 + jl];
                float ch = Cs[r * 132 + 96 + jl];
                size_t so = (size_t)grow * 256 + j;
                float hold = __half2float(g_st_h[cur][so]) + __half2float(g_st_l[cur][so]);
                float rg = 1.0f / (1.0f + expf(-(cr + br)));
                float zg = 1.0f / (1.0f + expf(-(cz + bz)));
                float nn = tanhf(ci + bi + rg * (ch + bhn));
                float v = (1.0f - zg) * nn + zg * hold;
                __half hh, hl;
                split2(v, hh, hl);
                g_st_h[nxt][so] = hh;
                g_st_l[nxt][so] = hl;
            }
        }
    }
}

// ============ K2: logits GEMM (fp16 split mma) ============
// grid (4 vblk, 128 rowblk), 256 thr. C tile 128 x 128 v. K = 256. 3-stage pipe.
#define K2_SMEM (3 * 32768)
__global__ __launch_bounds__(256, 2)
void k2_mma(int nxt, const float* __restrict__ bout) {
    extern __shared__ char smem[];
    const uint32_t sbase = smem_u32(smem);
    const int tid = threadIdx.x;
    const int lane = tid & 31, wid = tid >> 5;
    const int wm = wid & 1, wn = wid >> 1;
    const int v0 = blockIdx.x * 128;
    const int rbase = blockIdx.y * 128;

    const int arow = tid >> 1, ahalf = tid & 1;
    const uint32_t sw0 = SWM(arow, ahalf * 2);
    const uint32_t sw1 = SWM(arow, ahalf * 2 + 1);

    float acc[4][4][4];
#pragma unroll
    for (int i = 0; i < 4; i++)
#pragma unroll
        for (int j = 0; j < 4; j++)
#pragma unroll
            for (int q = 0; q < 4; q++) acc[i][j][q] = 0.0f;

    auto stage = [&](int c, int buf) {
        uint32_t ab = sbase + buf * 32768;
        size_t off = (size_t)(rbase + arow) * 256 + c * 32 + ahalf * 16;
        cpa16(ab + sw0, g_st_h[nxt] + off);
        cpa16(ab + sw1, g_st_h[nxt] + off + 8);
        cpa16(ab + 8192 + sw0, g_st_l[nxt] + off);
        cpa16(ab + 8192 + sw1, g_st_l[nxt] + off + 8);
        size_t offb = (size_t)(v0 + arow) * 256 + c * 32 + ahalf * 16;
        cpa16(ab + 16384 + sw0, g_Wo_h + offb);
        cpa16(ab + 16384 + sw1, g_Wo_h + offb + 8);
        cpa16(ab + 24576 + sw0, g_Wo_l + offb);
        cpa16(ab + 24576 + sw1, g_Wo_l + offb + 8);
    };

    stage(0, 0);
    asm volatile("cp.async.commit_group;");
    stage(1, 1);
    asm volatile("cp.async.commit_group;");

    for (int c = 0; c < 8; c++) {
        if (c < 7) asm volatile("cp.async.wait_group 1;");
        else       asm volatile("cp.async.wait_group 0;");
        __syncthreads();
        if (c < 6) {
            stage(c + 2, (c + 2) % 3);
            asm volatile("cp.async.commit_group;");
        }
        uint32_t ab = sbase + (c % 3) * 32768;
#pragma unroll
        for (int q = 0; q < 2; q++) {
            int gb = q * 2;
            uint32_t aAddr[4], bAddr[4];
            {
                int rl = wm * 64 + (lane & 15);
                int ga = gb + (lane >> 4);
#pragma unroll
                for (int mt = 0; mt < 4; mt++) {
                    int row = rl + mt * 16;
                    aAddr[mt] = ab + SWM(row, ga);
                }
                int rb = wn * 32 + (lane & 7);
                int gbb = gb + ((lane >> 3) & 1);
#pragma unroll
                for (int nt = 0; nt < 4; nt++) {
                    int row = rb + nt * 8;
                    bAddr[nt] = ab + 16384 + SWM(row, gbb);
                }
            }
            uint32_t af[4][4], bh[4][2], bl[4][2];
#pragma unroll
            for (int mt = 0; mt < 4; mt++) ldm4(af[mt], aAddr[mt]);
#pragma unroll
            for (int nt = 0; nt < 4; nt++) ldm2(bh[nt], bAddr[nt]);
#pragma unroll
            for (int mt = 0; mt < 4; mt++)
#pragma unroll
                for (int nt = 0; nt < 4; nt++) mma16816(acc[mt][nt], af[mt], bh[nt]);
#pragma unroll
            for (int nt = 0; nt < 4; nt++) ldm2(bl[nt], bAddr[nt] + 8192);
#pragma unroll
            for (int mt = 0; mt < 4; mt++)
#pragma unroll
                for (int nt = 0; nt < 4; nt++) mma16816(acc[mt][nt], af[mt], bl[nt]);
#pragma unroll
            for (int mt = 0; mt < 4; mt++) ldm4(af[mt], aAddr[mt] + 8192);
#pragma unroll
            for (int mt = 0; mt < 4; mt++)
#pragma unroll
                for (int nt = 0; nt < 4; nt++) mma16816(acc[mt][nt], af[mt], bh[nt]);
        }
    }

    // direct store with bias
#pragma unroll
    for (int nt = 0; nt < 4; nt++) {
        int c0 = v0 + wn * 32 + nt * 8 + (lane & 3) * 2;
        float b0 = bout[c0], b1 = bout[c0 + 1];
#pragma unroll
        for (int mt = 0; mt < 4; mt++) {
            int r0 = rbase + wm * 64 + mt * 16 + (lane >> 2);
            float2 s0 = make_float2(acc[mt][nt][0] + b0, acc[mt][nt][1] + b1);
            float2 s1 = make_float2(acc[mt][nt][2] + b0, acc[mt][nt][3] + b1);
            *(float2*)&g_logits[(size_t)r0 * NV + c0] = s0;
            *(float2*)&g_logits[(size_t)(r0 + 8) * NV + c0] = s1;
        }
    }
}

// ---------------- K3: gumbel sample + bookkeeping (bit-exact, proven) ----------------
__global__ __launch_bounds__(256)
void k3_kernel(int t, float* __restrict__ out) {
    int gw = (blockIdx.x * blockDim.x + threadIdx.x) >> 5;
    int lane = threadIdx.x & 31;
    if (gw >= NB) return;
    uint32_t k0 = g_keys[t][0], k1 = g_keys[t][1];
    const float TINY = 1.17549435e-38f;

    float xv[16];
    float vb = -3.4e38f;
    int ib = 0;
    float m = -3.4e38f;
#pragma unroll
    for (int i = 0; i < 16; i++) {
        int v = lane + 32 * i;
        float x = g_logits[gw * NV + v];
        xv[i] = x;
        uint32_t idx = (uint32_t)(gw * NV + v);
        uint32_t o0, o1;
        tfry(k0, k1, 0u, idx, o0, o1);
        uint32_t bits = o0 ^ o1;
        float f = __uint_as_float((bits >> 9) | 0x3f800000u) - 1.0f;
        float u = fmaxf(TINY, f * (1.0f - TINY) + TINY);
        float g = -logf(-logf(u));
        float val = x + g;
        if (val > vb) { vb = val; ib = v; }
        m = fmaxf(m, x);
    }
#pragma unroll
    for (int off = 16; off > 0; off >>= 1) {
        float ov = __shfl_xor_sync(0xffffffffu, vb, off);
        int oi = __shfl_xor_sync(0xffffffffu, ib, off);
        float om = __shfl_xor_sync(0xffffffffu, m, off);
        if (ov > vb || (ov == vb && oi < ib)) { vb = ov; ib = oi; }
        m = fmaxf(m, om);
    }
    float s = 0.0f;
#pragma unroll
    for (int i = 0; i < 16; i++) s += expf(xv[i] - m);
#pragma unroll
    for (int off = 16; off > 0; off >>= 1)
        s += __shfl_xor_sync(0xffffffffu, s, off);

    if (lane == 0) {
        int tok = ib;
        float xt = g_logits[gw * NV + tok];
        float lp = (xt - m) - logf(s);
        int alive = g_alive[gw];
        if (alive) g_logp[gw] += lp;
        int tok_out = alive ? tok : 0;
        if (alive && tok == 0) g_N[gw] = t + 1;
        g_alive[gw] = (alive && tok != 0) ? 1 : 0;
        g_tok[gw] = tok_out;
        out[gw * NT + t] = (float)tok_out;
    }
}

__global__ void fin_kernel(float* __restrict__ out) {
    int b = blockIdx.x * blockDim.x + threadIdx.x;
    if (b < NB) {
        out[NB * NT + b] = (float)g_N[b];
        out[NB * NT + NB + b] = g_logp[b];
    }
}

extern "C" void kernel_launch(void* const* d_in, const int* in_sizes, int n_in,
                              void* d_out, int out_size) {
    const int* actions = (const int*)d_in[0];
    const float* h1 = (const float*)d_in[2];
    const float* d2e = (const float*)d_in[3];
    const float* Wih = (const float*)d_in[4];
    const float* Whh = (const float*)d_in[5];
    const float* bih = (const float*)d_in[6];
    const float* bhh = (const float*)d_in[7];
    const float* Wout = (const float*)d_in[8];
    const float* bout = (const float*)d_in[9];
    float* out = (float*)d_out;

    cudaFuncSetAttribute(k1_mma, cudaFuncAttributeMaxDynamicSharedMemorySize, K1_SMEM);
    cudaFuncSetAttribute(k2_mma, cudaFuncAttributeMaxDynamicSharedMemorySize, K2_SMEM);

    prep_kernel<<<1024, 256>>>(Wih, Whh, Wout, d2e);
    init_kernel<<<2048, 256>>>(actions, h1);
    for (int t = 0; t < NT; t++) {
        int cur = t & 1;
        k1_mma<<<dim3(8, 128), 256, K1_SMEM>>>(cur, bih, bhh);
        k2_mma<<<dim3(4, 128), 256, K2_SMEM>>>(cur ^ 1, bout);
        k3_kernel<<<2048, 256>>>(t, out);
    }
    fin_kernel<<<64, 256>>>(out);
}

// round 7
// speedup vs baseline: 2.5237x; 1.4052x over previous
#include <cuda_runtime.h>
#include <cuda_fp16.h>
#include <cstdint>

#define NB 16384
#define NE 256
#define NV 512
#define NT 16

// ---------------- scratch ----------------
__device__ __half g_st_h[2][NB * NE];
__device__ __half g_st_l[2][NB * NE];
__device__ __half g_GN_h[768 * 256];     // W_hh split (r,z,n stacked) [np][k]
__device__ __half g_GN_l[768 * 256];
__device__ __half g_Wo_h[NV * NE];
__device__ __half g_Wo_l[NV * NE];
__device__ float g_WihT[256 * 768];      // W_ih transposed [k][np]
__device__ float g_T[512 * 768];         // token gate table (fp32 exact)
__device__ float g_logits[NB * NV];
__device__ int g_tok[NB];
__device__ int g_alive[NB];
__device__ int g_N[NB];
__device__ float g_logp[NB];
__device__ uint32_t g_keys[NT][2];

// swizzled 16B-group byte offset within a [rows][32 fp16] tile
#define SWM(row, g) ((((row) * 4) + ((g) ^ ((((row) >> 1)) & 3))) * 16)

__device__ __forceinline__ uint32_t smem_u32(const void* p) {
    uint32_t a;
    asm("{ .reg .u64 t; cvta.to.shared.u64 t, %1; cvt.u32.u64 %0, t; }" : "=r"(a) : "l"(p));
    return a;
}
__device__ __forceinline__ void cpa16(uint32_t s, const void* g) {
    asm volatile("cp.async.ca.shared.global [%0], [%1], 16;" :: "r"(s), "l"(g));
}
__device__ __forceinline__ void ldm4(uint32_t* r, uint32_t a) {
    asm volatile("ldmatrix.sync.aligned.m8n8.x4.shared.b16 {%0,%1,%2,%3}, [%4];"
                 : "=r"(r[0]), "=r"(r[1]), "=r"(r[2]), "=r"(r[3]) : "r"(a));
}
__device__ __forceinline__ void ldm2(uint32_t* r, uint32_t a) {
    asm volatile("ldmatrix.sync.aligned.m8n8.x2.shared.b16 {%0,%1}, [%2];"
                 : "=r"(r[0]), "=r"(r[1]) : "r"(a));
}
__device__ __forceinline__ void mma16816(float* c, const uint32_t* a, const uint32_t* b) {
    asm volatile(
        "mma.sync.aligned.m16n8k16.row.col.f32.f16.f16.f32 "
        "{%0,%1,%2,%3}, {%4,%5,%6,%7}, {%8,%9}, {%0,%1,%2,%3};"
        : "+f"(c[0]), "+f"(c[1]), "+f"(c[2]), "+f"(c[3])
        : "r"(a[0]), "r"(a[1]), "r"(a[2]), "r"(a[3]), "r"(b[0]), "r"(b[1]));
}
__device__ __forceinline__ void split2(float v, __half& h, __half& l) {
    h = __float2half(v);
    l = __float2half(v - __half2float(h));
}

// ---------------- threefry ----------------
__device__ __forceinline__ uint32_t rotl32(uint32_t v, int r) {
    return (v << r) | (v >> (32 - r));
}
__device__ __forceinline__ void tfry(uint32_t k0, uint32_t k1,
                                     uint32_t c0, uint32_t c1,
                                     uint32_t& o0, uint32_t& o1) {
    uint32_t k2 = k0 ^ k1 ^ 0x1BD11BDAu;
    uint32_t x0 = c0 + k0, x1 = c1 + k1;
#define R4(a,b,c,d) { x0+=x1; x1=rotl32(x1,a); x1^=x0; x0+=x1; x1=rotl32(x1,b); x1^=x0; \
                      x0+=x1; x1=rotl32(x1,c); x1^=x0; x0+=x1; x1=rotl32(x1,d); x1^=x0; }
    R4(13,15,26,6)  x0 += k1; x1 += k2 + 1u;
    R4(17,29,16,24) x0 += k2; x1 += k0 + 2u;
    R4(13,15,26,6)  x0 += k0; x1 += k1 + 3u;
    R4(17,29,16,24) x0 += k1; x1 += k2 + 4u;
    R4(13,15,26,6)  x0 += k2; x1 += k0 + 5u;
#undef R4
    o0 = x0; o1 = x1;
}

// ---------------- prep ----------------
__global__ void prep_kernel(const float* __restrict__ Wih,
                            const float* __restrict__ Whh,
                            const float* __restrict__ Wout) {
    int tid = blockIdx.x * blockDim.x + threadIdx.x;
    int stride = gridDim.x * blockDim.x;
    // GN = W_hh rows (r,z,n) as-is, split h/l
    for (int i = tid; i < 768 * 256; i += stride) {
        __half h, l; split2(Whh[i], h, l);
        g_GN_h[i] = h; g_GN_l[i] = l;
    }
    // WihT[k][np]
    for (int i = tid; i < 256 * 768; i += stride) {
        int k = i / 768, np = i - k * 768;
        g_WihT[i] = Wih[np * 256 + k];
    }
    for (int i = tid; i < NV * NE; i += stride) {
        __half h, l;
        split2(Wout[i], h, l);
        g_Wo_h[i] = h; g_Wo_l[i] = l;
    }
    if (blockIdx.x == 0 && threadIdx.x == 0) {
        for (int t = 0; t < NT; t++) {
            uint32_t a, b;
            tfry(0u, 42u, 0u, (uint32_t)t, a, b);
            g_keys[t][0] = a; g_keys[t][1] = b;
        }
    }
}

// T[tok][np] = d2e[tok] . Wih[np] + bih[np] + (np<512 ? bhh[np] : 0)   (fp32 exact)
__global__ __launch_bounds__(256)
void tgemm_kernel(const float* __restrict__ d2e,
                  const float* __restrict__ bih,
                  const float* __restrict__ bhh) {
    __shared__ float es[8][256];
    int tokbase = blockIdx.x * 8;
    int tid = threadIdx.x;
    for (int i = tid; i < 8 * 256; i += 256)
        es[i >> 8][i & 255] = d2e[(tokbase + (i >> 8)) * 256 + (i & 255)];
    __syncthreads();
#pragma unroll
    for (int p = 0; p < 3; p++) {
        int np = tid + p * 256;
        float acc[8];
        float bias = bih[np] + (np < 512 ? bhh[np] : 0.0f);
#pragma unroll
        for (int t = 0; t < 8; t++) acc[t] = 0.0f;
        for (int k = 0; k < 256; k++) {
            float w = g_WihT[k * 768 + np];
#pragma unroll
            for (int t = 0; t < 8; t++) acc[t] += es[t][k] * w;
        }
#pragma unroll
        for (int t = 0; t < 8; t++)
            g_T[(tokbase + t) * 768 + np] = acc[t] + bias;
    }
}

__global__ void init_kernel(const int* __restrict__ actions,
                            const float* __restrict__ h1) {
    int tid = blockIdx.x * blockDim.x + threadIdx.x;
    int stride = gridDim.x * blockDim.x;
    for (int i = tid; i < NB * NE; i += stride) {
        int b = i >> 8, e = i & 255;
        float v = h1[actions[b] * NE + e];
        __half h, l; split2(v, h, l);
        g_st_h[0][i] = h; g_st_l[0][i] = l;
    }
    for (int i = tid; i < NB; i += stride) {
        g_tok[i] = 0; g_alive[i] = 1; g_N[i] = NT; g_logp[i] = 0.0f;
    }
}

// ============ K1: state @ Whh^T (3 gates) + token-table GRU epilogue ============
// grid (8 jblk, 128 rowblk), 256 thr. C tile 128 rows x 96 N (r|z|n x 32 j). K=256.
// stage = A(h,l) 16KB + B(h,l) 12KB = 28KB; 3 stages = 84KB. 8 warps at 32x48.
#define K1_STAGE 28672
#define K1_SMEM (3 * K1_STAGE)
__global__ __launch_bounds__(256, 2)
void k1_mma(int cur, const float* __restrict__ bhh) {
    extern __shared__ char smem[];
    const uint32_t sbase = smem_u32(smem);
    const int tid = threadIdx.x;
    const int lane = tid & 31, wid = tid >> 5;
    const int wm = wid & 3, wn = wid >> 2;      // 4 m-blocks x 2 n-blocks
    const int j0 = blockIdx.x * 32;
    const int rbase = blockIdx.y * 128;
    const int nxt = cur ^ 1;

    const int arow = tid >> 1, ahalf = tid & 1;
    const uint32_t sw0 = SWM(arow, ahalf * 2);
    const uint32_t sw1 = SWM(arow, ahalf * 2 + 1);
    const size_t aoff = (size_t)(rbase + arow) * 256 + ahalf * 16;

    float acc[2][6][4];
#pragma unroll
    for (int i = 0; i < 2; i++)
#pragma unroll
        for (int j = 0; j < 6; j++)
#pragma unroll
            for (int q = 0; q < 4; q++) acc[i][j][q] = 0.0f;

    // B-op mapping (3 per thread)
    int b_brow[3], b_grp[3], b_half[3];
    size_t b_src[3];
    uint32_t b_dst[3];
#pragma unroll
    for (int i = 0; i < 3; i++) {
        int o = tid + 256 * i;
        int half = o >= 384;
        int rem = o - half * 384;
        int brow = rem >> 2, grp = rem & 3;
        b_brow[i] = brow; b_grp[i] = grp; b_half[i] = half;
        int grow = (brow >> 5) * 256 + j0 + (brow & 31);
        b_src[i] = (size_t)grow * 256 + grp * 8;
        b_dst[i] = 16384 + half * 6144 + SWM(brow, grp);
    }

    auto stage = [&](int c, int buf) {
        uint32_t ab = sbase + buf * K1_STAGE;
        size_t off = aoff + c * 32;
        cpa16(ab + sw0, g_st_h[cur] + off);
        cpa16(ab + sw1, g_st_h[cur] + off + 8);
        cpa16(ab + 8192 + sw0, g_st_l[cur] + off);
        cpa16(ab + 8192 + sw1, g_st_l[cur] + off + 8);
#pragma unroll
        for (int i = 0; i < 3; i++) {
            const __half* src = (b_half[i] ? g_GN_l : g_GN_h) + b_src[i] + c * 32;
            cpa16(ab + b_dst[i], src);
        }
    };

    stage(0, 0);
    asm volatile("cp.async.commit_group;");
    stage(1, 1);
    asm volatile("cp.async.commit_group;");

    for (int c = 0; c < 8; c++) {
        if (c < 7) asm volatile("cp.async.wait_group 1;");
        else       asm volatile("cp.async.wait_group 0;");
        __syncthreads();
        if (c < 6) {
            stage(c + 2, (c + 2) % 3);
            asm volatile("cp.async.commit_group;");
        }
        uint32_t ab = sbase + (c % 3) * K1_STAGE;
#pragma unroll
        for (int q = 0; q < 2; q++) {
            int gb = q * 2;
            uint32_t aAddr[2], bAddr[6];
            {
                int rl = wm * 32 + (lane & 15);
                int ga = gb + (lane >> 4);
#pragma unroll
                for (int mt = 0; mt < 2; mt++)
                    aAddr[mt] = ab + SWM(rl + mt * 16, ga);
                int rb0 = wn * 48 + (lane & 7);
                int gbb = gb + ((lane >> 3) & 1);
#pragma unroll
                for (int nt = 0; nt < 6; nt++)
                    bAddr[nt] = ab + 16384 + SWM(rb0 + nt * 8, gbb);
            }
            uint32_t af[2][4], bh[6][2], bl[6][2];
#pragma unroll
            for (int mt = 0; mt < 2; mt++) ldm4(af[mt], aAddr[mt]);
#pragma unroll
            for (int nt = 0; nt < 6; nt++) ldm2(bh[nt], bAddr[nt]);
#pragma unroll
            for (int mt = 0; mt < 2; mt++)
#pragma unroll
                for (int nt = 0; nt < 6; nt++) mma16816(acc[mt][nt], af[mt], bh[nt]);
#pragma unroll
            for (int nt = 0; nt < 6; nt++) ldm2(bl[nt], bAddr[nt] + 6144);
#pragma unroll
            for (int mt = 0; mt < 2; mt++)
#pragma unroll
                for (int nt = 0; nt < 6; nt++) mma16816(acc[mt][nt], af[mt], bl[nt]);
#pragma unroll
            for (int mt = 0; mt < 2; mt++) ldm4(af[mt], aAddr[mt] + 8192);
#pragma unroll
            for (int mt = 0; mt < 2; mt++)
#pragma unroll
                for (int nt = 0; nt < 6; nt++) mma16816(acc[mt][nt], af[mt], bh[nt]);
        }
    }

    // ---- epilogue: dump C to smem, token-table GRU, split-store state ----
    float* Cs = (float*)smem;   // [128][100] fp32 (51.2KB <= 84KB)
    __syncthreads();
#pragma unroll
    for (int mt = 0; mt < 2; mt++)
#pragma unroll
        for (int nt = 0; nt < 6; nt++) {
            int r0 = wm * 32 + mt * 16 + (lane >> 2);
            int c0 = wn * 48 + nt * 8 + (lane & 3) * 2;
            Cs[r0 * 100 + c0] = acc[mt][nt][0];
            Cs[r0 * 100 + c0 + 1] = acc[mt][nt][1];
            Cs[(r0 + 8) * 100 + c0] = acc[mt][nt][2];
            Cs[(r0 + 8) * 100 + c0 + 1] = acc[mt][nt][3];
        }
    __syncthreads();
    {
        int jl = tid & 31, rseg = tid >> 5;
        int j = j0 + jl;
        float bhn = bhh[512 + j];
#pragma unroll
        for (int rr = 0; rr < 16; rr++) {
            int r = rseg * 16 + rr;
            int grow = rbase + r;
            int tok = g_tok[grow];
            const float* Trow = g_T + (size_t)tok * 768;
            float cr = Cs[r * 100 + jl] + Trow[j];
            float cz = Cs[r * 100 + 32 + jl] + Trow[256 + j];
            float cn = Cs[r * 100 + 64 + jl] + bhn;
            size_t so = (size_t)grow * 256 + j;
            float hold = __half2float(g_st_h[cur][so]) + __half2float(g_st_l[cur][so]);
            float rg = 1.0f / (1.0f + expf(-cr));
            float zg = 1.0f / (1.0f + expf(-cz));
            float nn = tanhf(Trow[512 + j] + rg * cn);
            float v = (1.0f - zg) * nn + zg * hold;
            __half hh, hl;
            split2(v, hh, hl);
            g_st_h[nxt][so] = hh;
            g_st_l[nxt][so] = hl;
        }
    }
}

// ============ K2: logits GEMM (fp16 split mma) ============
// grid (4 vblk, 128 rowblk), 256 thr. C tile 128 x 128 v. K = 256. 3-stage pipe.
#define K2_SMEM (3 * 32768)
__global__ __launch_bounds__(256, 2)
void k2_mma(int nxt, const float* __restrict__ bout) {
    extern __shared__ char smem[];
    const uint32_t sbase = smem_u32(smem);
    const int tid = threadIdx.x;
    const int lane = tid & 31, wid = tid >> 5;
    const int wm = wid & 1, wn = wid >> 1;
    const int v0 = blockIdx.x * 128;
    const int rbase = blockIdx.y * 128;

    const int arow = tid >> 1, ahalf = tid & 1;
    const uint32_t sw0 = SWM(arow, ahalf * 2);
    const uint32_t sw1 = SWM(arow, ahalf * 2 + 1);

    float acc[4][4][4];
#pragma unroll
    for (int i = 0; i < 4; i++)
#pragma unroll
        for (int j = 0; j < 4; j++)
#pragma unroll
            for (int q = 0; q < 4; q++) acc[i][j][q] = 0.0f;

    auto stage = [&](int c, int buf) {
        uint32_t ab = sbase + buf * 32768;
        size_t off = (size_t)(rbase + arow) * 256 + c * 32 + ahalf * 16;
        cpa16(ab + sw0, g_st_h[nxt] + off);
        cpa16(ab + sw1, g_st_h[nxt] + off + 8);
        cpa16(ab + 8192 + sw0, g_st_l[nxt] + off);
        cpa16(ab + 8192 + sw1, g_st_l[nxt] + off + 8);
        size_t offb = (size_t)(v0 + arow) * 256 + c * 32 + ahalf * 16;
        cpa16(ab + 16384 + sw0, g_Wo_h + offb);
        cpa16(ab + 16384 + sw1, g_Wo_h + offb + 8);
        cpa16(ab + 24576 + sw0, g_Wo_l + offb);
        cpa16(ab + 24576 + sw1, g_Wo_l + offb + 8);
    };

    stage(0, 0);
    asm volatile("cp.async.commit_group;");
    stage(1, 1);
    asm volatile("cp.async.commit_group;");

    for (int c = 0; c < 8; c++) {
        if (c < 7) asm volatile("cp.async.wait_group 1;");
        else       asm volatile("cp.async.wait_group 0;");
        __syncthreads();
        if (c < 6) {
            stage(c + 2, (c + 2) % 3);
            asm volatile("cp.async.commit_group;");
        }
        uint32_t ab = sbase + (c % 3) * 32768;
#pragma unroll
        for (int q = 0; q < 2; q++) {
            int gb = q * 2;
            uint32_t aAddr[4], bAddr[4];
            {
                int rl = wm * 64 + (lane & 15);
                int ga = gb + (lane >> 4);
#pragma unroll
                for (int mt = 0; mt < 4; mt++) {
                    int row = rl + mt * 16;
                    aAddr[mt] = ab + SWM(row, ga);
                }
                int rb = wn * 32 + (lane & 7);
                int gbb = gb + ((lane >> 3) & 1);
#pragma unroll
                for (int nt = 0; nt < 4; nt++) {
                    int row = rb + nt * 8;
                    bAddr[nt] = ab + 16384 + SWM(row, gbb);
                }
            }
            uint32_t af[4][4], bh[4][2], bl[4][2];
#pragma unroll
            for (int mt = 0; mt < 4; mt++) ldm4(af[mt], aAddr[mt]);
#pragma unroll
            for (int nt = 0; nt < 4; nt++) ldm2(bh[nt], bAddr[nt]);
#pragma unroll
            for (int mt = 0; mt < 4; mt++)
#pragma unroll
                for (int nt = 0; nt < 4; nt++) mma16816(acc[mt][nt], af[mt], bh[nt]);
#pragma unroll
            for (int nt = 0; nt < 4; nt++) ldm2(bl[nt], bAddr[nt] + 8192);
#pragma unroll
            for (int mt = 0; mt < 4; mt++)
#pragma unroll
                for (int nt = 0; nt < 4; nt++) mma16816(acc[mt][nt], af[mt], bl[nt]);
#pragma unroll
            for (int mt = 0; mt < 4; mt++) ldm4(af[mt], aAddr[mt] + 8192);
#pragma unroll
            for (int mt = 0; mt < 4; mt++)
#pragma unroll
                for (int nt = 0; nt < 4; nt++) mma16816(acc[mt][nt], af[mt], bh[nt]);
        }
    }

    // direct store with bias
#pragma unroll
    for (int nt = 0; nt < 4; nt++) {
        int c0 = v0 + wn * 32 + nt * 8 + (lane & 3) * 2;
        float b0 = bout[c0], b1 = bout[c0 + 1];
#pragma unroll
        for (int mt = 0; mt < 4; mt++) {
            int r0 = rbase + wm * 64 + mt * 16 + (lane >> 2);
            float2 s0 = make_float2(acc[mt][nt][0] + b0, acc[mt][nt][1] + b1);
            float2 s1 = make_float2(acc[mt][nt][2] + b0, acc[mt][nt][3] + b1);
            *(float2*)&g_logits[(size_t)r0 * NV + c0] = s0;
            *(float2*)&g_logits[(size_t)(r0 + 8) * NV + c0] = s1;
        }
    }
}

// ---------------- K3: gumbel sample + bookkeeping (bit-exact, proven) ----------------
__global__ __launch_bounds__(256)
void k3_kernel(int t, float* __restrict__ out) {
    int gw = (blockIdx.x * blockDim.x + threadIdx.x) >> 5;
    int lane = threadIdx.x & 31;
    if (gw >= NB) return;
    uint32_t k0 = g_keys[t][0], k1 = g_keys[t][1];
    const float TINY = 1.17549435e-38f;

    float xv[16];
    float vb = -3.4e38f;
    int ib = 0;
    float m = -3.4e38f;
#pragma unroll
    for (int i = 0; i < 16; i++) {
        int v = lane + 32 * i;
        float x = g_logits[gw * NV + v];
        xv[i] = x;
        uint32_t idx = (uint32_t)(gw * NV + v);
        uint32_t o0, o1;
        tfry(k0, k1, 0u, idx, o0, o1);
        uint32_t bits = o0 ^ o1;
        float f = __uint_as_float((bits >> 9) | 0x3f800000u) - 1.0f;
        float u = fmaxf(TINY, f * (1.0f - TINY) + TINY);
        float g = -logf(-logf(u));
        float val = x + g;
        if (val > vb) { vb = val; ib = v; }
        m = fmaxf(m, x);
    }
#pragma unroll
    for (int off = 16; off > 0; off >>= 1) {
        float ov = __shfl_xor_sync(0xffffffffu, vb, off);
        int oi = __shfl_xor_sync(0xffffffffu, ib, off);
        float om = __shfl_xor_sync(0xffffffffu, m, off);
        if (ov > vb || (ov == vb && oi < ib)) { vb = ov; ib = oi; }
        m = fmaxf(m, om);
    }
    float s = 0.0f;
#pragma unroll
    for (int i = 0; i < 16; i++) s += expf(xv[i] - m);
#pragma unroll
    for (int off = 16; off > 0; off >>= 1)
        s += __shfl_xor_sync(0xffffffffu, s, off);

    if (lane == 0) {
        int tok = ib;
        float xt = g_logits[gw * NV + tok];
        float lp = (xt - m) - logf(s);
        int alive = g_alive[gw];
        if (alive) g_logp[gw] += lp;
        int tok_out = alive ? tok : 0;
        if (alive && tok == 0) g_N[gw] = t + 1;
        g_alive[gw] = (alive && tok != 0) ? 1 : 0;
        g_tok[gw] = tok_out;
        out[gw * NT + t] = (float)tok_out;
    }
}

__global__ void fin_kernel(float* __restrict__ out) {
    int b = blockIdx.x * blockDim.x + threadIdx.x;
    if (b < NB) {
        out[NB * NT + b] = (float)g_N[b];
        out[NB * NT + NB + b] = g_logp[b];
    }
}

extern "C" void kernel_launch(void* const* d_in, const int* in_sizes, int n_in,
                              void* d_out, int out_size) {
    const int* actions = (const int*)d_in[0];
    const float* h1 = (const float*)d_in[2];
    const float* d2e = (const float*)d_in[3];
    const float* Wih = (const float*)d_in[4];
    const float* Whh = (const float*)d_in[5];
    const float* bih = (const float*)d_in[6];
    const float* bhh = (const float*)d_in[7];
    const float* Wout = (const float*)d_in[8];
    const float* bout = (const float*)d_in[9];
    float* out = (float*)d_out;

    cudaFuncSetAttribute(k1_mma, cudaFuncAttributeMaxDynamicSharedMemorySize, K1_SMEM);
    cudaFuncSetAttribute(k2_mma, cudaFuncAttributeMaxDynamicSharedMemorySize, K2_SMEM);

    prep_kernel<<<1024, 256>>>(Wih, Whh, Wout);
    tgemm_kernel<<<64, 256>>>(d2e, bih, bhh);
    init_kernel<<<2048, 256>>>(actions, h1);
    for (int t = 0; t < NT; t++) {
        int cur = t & 1;
        k1_mma<<<dim3(8, 128), 256, K1_SMEM>>>(cur, bhh);
        k2_mma<<<dim3(4, 128), 256, K2_SMEM>>>(cur ^ 1, bout);
        k3_kernel<<<2048, 256>>>(t, out);
    }
    fin_kernel<<<64, 256>>>(out);
}

// round 8
// speedup vs baseline: 2.5680x; 1.0175x over previous
#include <cuda_runtime.h>
#include <cuda_fp16.h>
#include <cstdint>

#define NB 16384
#define NE 256
#define NV 512
#define NT 16

// ---------------- scratch ----------------
__device__ __half g_st_h[2][NB * NE];
__device__ __half g_st_l[2][NB * NE];
__device__ __half g_GN_h[768 * 256];     // W_hh split (r,z,n stacked) [np][k]
__device__ __half g_GN_l[768 * 256];
__device__ __half g_Wo_h[NV * NE];
__device__ __half g_Wo_l[NV * NE];
__device__ float g_WihT[256 * 768];      // W_ih transposed [k][np]
__device__ float g_T[512 * 768];         // token gate table (fp32 exact)
__device__ float g_noise[NB * NV];       // gumbel noise for current step
__device__ float4 g_partA[NB * 4];       // (bestval, idx-bits, x_best, M) per vblk
__device__ float g_partB[NB * 4];        // sumexp per vblk
__device__ int g_alive[2][NB];
__device__ int g_N[NB];
__device__ float g_logp[NB];
__device__ uint32_t g_keys[NT][2];

#define SWM(row, g) ((((row) * 4) + ((g) ^ ((((row) >> 1)) & 3))) * 16)
#define TINYF 1.17549435e-38f

__device__ __forceinline__ uint32_t smem_u32(const void* p) {
    uint32_t a;
    asm("{ .reg .u64 t; cvta.to.shared.u64 t, %1; cvt.u32.u64 %0, t; }" : "=r"(a) : "l"(p));
    return a;
}
__device__ __forceinline__ void cpa16(uint32_t s, const void* g) {
    asm volatile("cp.async.ca.shared.global [%0], [%1], 16;" :: "r"(s), "l"(g));
}
__device__ __forceinline__ void ldm4(uint32_t* r, uint32_t a) {
    asm volatile("ldmatrix.sync.aligned.m8n8.x4.shared.b16 {%0,%1,%2,%3}, [%4];"
                 : "=r"(r[0]), "=r"(r[1]), "=r"(r[2]), "=r"(r[3]) : "r"(a));
}
__device__ __forceinline__ void ldm2(uint32_t* r, uint32_t a) {
    asm volatile("ldmatrix.sync.aligned.m8n8.x2.shared.b16 {%0,%1}, [%2];"
                 : "=r"(r[0]), "=r"(r[1]) : "r"(a));
}
__device__ __forceinline__ void mma16816(float* c, const uint32_t* a, const uint32_t* b) {
    asm volatile(
        "mma.sync.aligned.m16n8k16.row.col.f32.f16.f16.f32 "
        "{%0,%1,%2,%3}, {%4,%5,%6,%7}, {%8,%9}, {%0,%1,%2,%3};"
        : "+f"(c[0]), "+f"(c[1]), "+f"(c[2]), "+f"(c[3])
        : "r"(a[0]), "r"(a[1]), "r"(a[2]), "r"(a[3]), "r"(b[0]), "r"(b[1]));
}
__device__ __forceinline__ void split2(float v, __half& h, __half& l) {
    h = __float2half(v);
    l = __float2half(v - __half2float(h));
}

// ---------------- threefry ----------------
__device__ __forceinline__ uint32_t rotl32(uint32_t v, int r) {
    return (v << r) | (v >> (32 - r));
}
__device__ __forceinline__ void tfry(uint32_t k0, uint32_t k1,
                                     uint32_t c0, uint32_t c1,
                                     uint32_t& o0, uint32_t& o1) {
    uint32_t k2 = k0 ^ k1 ^ 0x1BD11BDAu;
    uint32_t x0 = c0 + k0, x1 = c1 + k1;
#define R4(a,b,c,d) { x0+=x1; x1=rotl32(x1,a); x1^=x0; x0+=x1; x1=rotl32(x1,b); x1^=x0; \
                      x0+=x1; x1=rotl32(x1,c); x1^=x0; x0+=x1; x1=rotl32(x1,d); x1^=x0; }
    R4(13,15,26,6)  x0 += k1; x1 += k2 + 1u;
    R4(17,29,16,24) x0 += k2; x1 += k0 + 2u;
    R4(13,15,26,6)  x0 += k0; x1 += k1 + 3u;
    R4(17,29,16,24) x0 += k1; x1 += k2 + 4u;
    R4(13,15,26,6)  x0 += k2; x1 += k0 + 5u;
#undef R4
    o0 = x0; o1 = x1;
}

// combine the 4 vblk partials for one row (deterministic; all callers agree)
__device__ __forceinline__ int combine_row(int grow, float* lp_out) {
    float4 pa[4];
    float sv[4];
#pragma unroll
    for (int i = 0; i < 4; i++) {
        pa[i] = g_partA[grow * 4 + i];
        sv[i] = g_partB[grow * 4 + i];
    }
    float M = fmaxf(fmaxf(pa[0].w, pa[1].w), fmaxf(pa[2].w, pa[3].w));
    float S = 0.0f;
#pragma unroll
    for (int i = 0; i < 4; i++) S += sv[i] * expf(pa[i].w - M);
    float bv = pa[0].x;
    int bi = __float_as_int(pa[0].y);
    float bx = pa[0].z;
#pragma unroll
    for (int i = 1; i < 4; i++) {
        int oi = __float_as_int(pa[i].y);
        if (pa[i].x > bv || (pa[i].x == bv && oi < bi)) {
            bv = pa[i].x; bi = oi; bx = pa[i].z;
        }
    }
    *lp_out = bx - M - logf(S);
    return bi;
}

// ---------------- prep ----------------
__global__ void prep_kernel(const float* __restrict__ Wih,
                            const float* __restrict__ Whh,
                            const float* __restrict__ Wout) {
    int tid = blockIdx.x * blockDim.x + threadIdx.x;
    int stride = gridDim.x * blockDim.x;
    for (int i = tid; i < 768 * 256; i += stride) {
        __half h, l; split2(Whh[i], h, l);
        g_GN_h[i] = h; g_GN_l[i] = l;
    }
    for (int i = tid; i < 256 * 768; i += stride) {
        int k = i / 768, np = i - k * 768;
        g_WihT[i] = Wih[np * 256 + k];
    }
    for (int i = tid; i < NV * NE; i += stride) {
        __half h, l;
        split2(Wout[i], h, l);
        g_Wo_h[i] = h; g_Wo_l[i] = l;
    }
    if (blockIdx.x == 0 && threadIdx.x == 0) {
        for (int t = 0; t < NT; t++) {
            uint32_t a, b;
            tfry(0u, 42u, 0u, (uint32_t)t, a, b);
            g_keys[t][0] = a; g_keys[t][1] = b;
        }
    }
}

// T[tok][np] = d2e[tok] . Wih[np] + bih[np] + (np<512 ? bhh[np] : 0)
__global__ __launch_bounds__(256)
void tgemm_kernel(const float* __restrict__ d2e,
                  const float* __restrict__ bih,
                  const float* __restrict__ bhh) {
    __shared__ float es[8][256];
    int tokbase = blockIdx.x * 8;
    int tid = threadIdx.x;
    for (int i = tid; i < 8 * 256; i += 256)
        es[i >> 8][i & 255] = d2e[(tokbase + (i >> 8)) * 256 + (i & 255)];
    __syncthreads();
#pragma unroll
    for (int p = 0; p < 3; p++) {
        int np = tid + p * 256;
        float acc[8];
        float bias = bih[np] + (np < 512 ? bhh[np] : 0.0f);
#pragma unroll
        for (int t = 0; t < 8; t++) acc[t] = 0.0f;
        for (int k = 0; k < 256; k++) {
            float w = g_WihT[k * 768 + np];
#pragma unroll
            for (int t = 0; t < 8; t++) acc[t] += es[t][k] * w;
        }
#pragma unroll
        for (int t = 0; t < 8; t++)
            g_T[(tokbase + t) * 768 + np] = acc[t] + bias;
    }
}

__global__ void init_kernel(const int* __restrict__ actions,
                            const float* __restrict__ h1) {
    int tid = blockIdx.x * blockDim.x + threadIdx.x;
    int stride = gridDim.x * blockDim.x;
    for (int i = tid; i < NB * NE; i += stride) {
        int b = i >> 8, e = i & 255;
        float v = h1[actions[b] * NE + e];
        __half h, l; split2(v, h, l);
        g_st_h[0][i] = h; g_st_l[0][i] = l;
    }
    for (int i = tid; i < NB; i += stride) {
        g_alive[0][i] = 1; g_N[i] = NT; g_logp[i] = 0.0f;
    }
}

// ============ K1: combine(t-1) + state @ Whh^T + noise-gen + GRU epilogue ============
#define K1_STAGE 28672
#define K1_SMEM (3 * K1_STAGE + 512)
__global__ __launch_bounds__(256, 2)
void k1_mma(int t, const float* __restrict__ bhh, float* __restrict__ out) {
    extern __shared__ char smem[];
    const uint32_t sbase = smem_u32(smem);
    const int tid = threadIdx.x;
    const int lane = tid & 31, wid = tid >> 5;
    const int wm = wid & 3, wn = wid >> 2;
    const int j0 = blockIdx.x * 32;
    const int jblk64 = blockIdx.x * 64;
    const int rbase = blockIdx.y * 128;
    const int cur = t & 1, nxt = cur ^ 1;
    int* tok_sm = (int*)(smem + 3 * K1_STAGE);

    const int arow = tid >> 1, ahalf = tid & 1;
    const uint32_t sw0 = SWM(arow, ahalf * 2);
    const uint32_t sw1 = SWM(arow, ahalf * 2 + 1);
    const size_t aoff = (size_t)(rbase + arow) * 256 + ahalf * 16;
    const uint32_t nk0 = g_keys[t][0], nk1 = g_keys[t][1];

    float acc[2][6][4];
#pragma unroll
    for (int i = 0; i < 2; i++)
#pragma unroll
        for (int j = 0; j < 6; j++)
#pragma unroll
            for (int q = 0; q < 4; q++) acc[i][j][q] = 0.0f;

    int b_half[3];
    size_t b_src[3];
    uint32_t b_dst[3];
#pragma unroll
    for (int i = 0; i < 3; i++) {
        int o = tid + 256 * i;
        int half = o >= 384;
        int rem = o - half * 384;
        int brow = rem >> 2, grp = rem & 3;
        b_half[i] = half;
        int grow = (brow >> 5) * 256 + j0 + (brow & 31);
        b_src[i] = (size_t)grow * 256 + grp * 8;
        b_dst[i] = 16384 + half * 6144 + SWM(brow, grp);
    }

    auto stage = [&](int c, int buf) {
        uint32_t ab = sbase + buf * K1_STAGE;
        size_t off = aoff + c * 32;
        cpa16(ab + sw0, g_st_h[cur] + off);
        cpa16(ab + sw1, g_st_h[cur] + off + 8);
        cpa16(ab + 8192 + sw0, g_st_l[cur] + off);
        cpa16(ab + 8192 + sw1, g_st_l[cur] + off + 8);
#pragma unroll
        for (int i = 0; i < 3; i++) {
            const __half* src = (b_half[i] ? g_GN_l : g_GN_h) + b_src[i] + c * 32;
            cpa16(ab + b_dst[i], src);
        }
    };

    stage(0, 0);
    asm volatile("cp.async.commit_group;");
    stage(1, 1);
    asm volatile("cp.async.commit_group;");

    // ---- prologue: combine step t-1 partials -> token (+ bookkeeping on jblk0)
    if (tid < 128) {
        int grow = rbase + tid;
        int tok_out = 0;
        if (t > 0) {
            float lp;
            int tok = combine_row(grow, &lp);
            int alive = g_alive[(t - 1) & 1][grow];
            tok_out = alive ? tok : 0;
            if (blockIdx.x == 0) {
                if (alive) g_logp[grow] += lp;
                if (alive && tok == 0) g_N[grow] = t;
                g_alive[t & 1][grow] = (alive && tok != 0) ? 1 : 0;
                out[(size_t)grow * NT + (t - 1)] = (float)tok_out;
            }
        }
        tok_sm[tid] = tok_out;
    }

    for (int c = 0; c < 8; c++) {
        if (c < 7) asm volatile("cp.async.wait_group 1;");
        else       asm volatile("cp.async.wait_group 0;");
        __syncthreads();
        if (c < 6) {
            stage(c + 2, (c + 2) % 3);
            asm volatile("cp.async.commit_group;");
        }
        uint32_t ab = sbase + (c % 3) * K1_STAGE;
#pragma unroll
        for (int q = 0; q < 2; q++) {
            int gb = q * 2;
            uint32_t aAddr[2], bAddr[6];
            {
                int rl = wm * 32 + (lane & 15);
                int ga = gb + (lane >> 4);
#pragma unroll
                for (int mt = 0; mt < 2; mt++)
                    aAddr[mt] = ab + SWM(rl + mt * 16, ga);
                int rb0 = wn * 48 + (lane & 7);
                int gbb = gb + ((lane >> 3) & 1);
#pragma unroll
                for (int nt = 0; nt < 6; nt++)
                    bAddr[nt] = ab + 16384 + SWM(rb0 + nt * 8, gbb);
            }
            uint32_t af[2][4], bh[6][2], bl[6][2];
#pragma unroll
            for (int mt = 0; mt < 2; mt++) ldm4(af[mt], aAddr[mt]);
#pragma unroll
            for (int nt = 0; nt < 6; nt++) ldm2(bh[nt], bAddr[nt]);
#pragma unroll
            for (int mt = 0; mt < 2; mt++)
#pragma unroll
                for (int nt = 0; nt < 6; nt++) mma16816(acc[mt][nt], af[mt], bh[nt]);
#pragma unroll
            for (int nt = 0; nt < 6; nt++) ldm2(bl[nt], bAddr[nt] + 6144);
#pragma unroll
            for (int mt = 0; mt < 2; mt++)
#pragma unroll
                for (int nt = 0; nt < 6; nt++) mma16816(acc[mt][nt], af[mt], bl[nt]);
#pragma unroll
            for (int mt = 0; mt < 2; mt++) ldm4(af[mt], aAddr[mt] + 8192);
#pragma unroll
            for (int mt = 0; mt < 2; mt++)
#pragma unroll
                for (int nt = 0; nt < 6; nt++) mma16816(acc[mt][nt], af[mt], bh[nt]);
        }
        // ---- hidden ALU: gumbel noise for this step's K2 (4 values/thread/chunk)
#pragma unroll
        for (int k = 0; k < 4; k++) {
            int vi = c * 1024 + k * 256 + tid;
            int row = vi >> 6, col = vi & 63;
            int grow = rbase + row;
            uint32_t idx = (uint32_t)(grow * NV + jblk64 + col);
            uint32_t o0, o1;
            tfry(nk0, nk1, 0u, idx, o0, o1);
            uint32_t bits = o0 ^ o1;
            float f = __uint_as_float((bits >> 9) | 0x3f800000u) - 1.0f;
            float u = fmaxf(TINYF, f * (1.0f - TINYF) + TINYF);
            g_noise[grow * NV + jblk64 + col] = -logf(-logf(u));
        }
    }

    // ---- epilogue: dump C, token-table GRU, split-store state ----
    float* Cs = (float*)smem;
    __syncthreads();
#pragma unroll
    for (int mt = 0; mt < 2; mt++)
#pragma unroll
        for (int nt = 0; nt < 6; nt++) {
            int r0 = wm * 32 + mt * 16 + (lane >> 2);
            int c0 = wn * 48 + nt * 8 + (lane & 3) * 2;
            Cs[r0 * 100 + c0] = acc[mt][nt][0];
            Cs[r0 * 100 + c0 + 1] = acc[mt][nt][1];
            Cs[(r0 + 8) * 100 + c0] = acc[mt][nt][2];
            Cs[(r0 + 8) * 100 + c0 + 1] = acc[mt][nt][3];
        }
    __syncthreads();
    {
        int jl = tid & 31, rseg = tid >> 5;
        int j = j0 + jl;
        float bhn = bhh[512 + j];
#pragma unroll
        for (int rr = 0; rr < 16; rr++) {
            int r = rseg * 16 + rr;
            int grow = rbase + r;
            int tok = tok_sm[r];
            const float* Trow = g_T + (size_t)tok * 768;
            float cr = Cs[r * 100 + jl] + Trow[j];
            float cz = Cs[r * 100 + 32 + jl] + Trow[256 + j];
            float cn = Cs[r * 100 + 64 + jl] + bhn;
            size_t so = (size_t)grow * 256 + j;
            float hold = __half2float(g_st_h[cur][so]) + __half2float(g_st_l[cur][so]);
            float rg = 1.0f / (1.0f + expf(-cr));
            float zg = 1.0f / (1.0f + expf(-cz));
            float nn = tanhf(Trow[512 + j] + rg * cn);
            float v = (1.0f - zg) * nn + zg * hold;
            __half hh, hl;
            split2(v, hh, hl);
            g_st_h[nxt][so] = hh;
            g_st_l[nxt][so] = hl;
        }
    }
}

// ============ K2: logits GEMM + fused gumbel-argmax partials ============
#define K2_SMEM (3 * 32768)
__global__ __launch_bounds__(256, 2)
void k2_mma(int nxt, const float* __restrict__ bout) {
    extern __shared__ char smem[];
    const uint32_t sbase = smem_u32(smem);
    const int tid = threadIdx.x;
    const int lane = tid & 31, wid = tid >> 5;
    const int wm = wid & 1, wn = wid >> 1;
    const int v0 = blockIdx.x * 128;
    const int rbase = blockIdx.y * 128;

    const int arow = tid >> 1, ahalf = tid & 1;
    const uint32_t sw0 = SWM(arow, ahalf * 2);
    const uint32_t sw1 = SWM(arow, ahalf * 2 + 1);

    float acc[4][4][4];
#pragma unroll
    for (int i = 0; i < 4; i++)
#pragma unroll
        for (int j = 0; j < 4; j++)
#pragma unroll
            for (int q = 0; q < 4; q++) acc[i][j][q] = 0.0f;

    auto stage = [&](int c, int buf) {
        uint32_t ab = sbase + buf * 32768;
        size_t off = (size_t)(rbase + arow) * 256 + c * 32 + ahalf * 16;
        cpa16(ab + sw0, g_st_h[nxt] + off);
        cpa16(ab + sw1, g_st_h[nxt] + off + 8);
        cpa16(ab + 8192 + sw0, g_st_l[nxt] + off);
        cpa16(ab + 8192 + sw1, g_st_l[nxt] + off + 8);
        size_t offb = (size_t)(v0 + arow) * 256 + c * 32 + ahalf * 16;
        cpa16(ab + 16384 + sw0, g_Wo_h + offb);
        cpa16(ab + 16384 + sw1, g_Wo_h + offb + 8);
        cpa16(ab + 24576 + sw0, g_Wo_l + offb);
        cpa16(ab + 24576 + sw1, g_Wo_l + offb + 8);
    };

    stage(0, 0);
    asm volatile("cp.async.commit_group;");
    stage(1, 1);
    asm volatile("cp.async.commit_group;");

    for (int c = 0; c < 8; c++) {
        if (c < 7) asm volatile("cp.async.wait_group 1;");
        else       asm volatile("cp.async.wait_group 0;");
        __syncthreads();
        if (c < 6) {
            stage(c + 2, (c + 2) % 3);
            asm volatile("cp.async.commit_group;");
        }
        uint32_t ab = sbase + (c % 3) * 32768;
#pragma unroll
        for (int q = 0; q < 2; q++) {
            int gb = q * 2;
            uint32_t aAddr[4], bAddr[4];
            {
                int rl = wm * 64 + (lane & 15);
                int ga = gb + (lane >> 4);
#pragma unroll
                for (int mt = 0; mt < 4; mt++)
                    aAddr[mt] = ab + SWM(rl + mt * 16, ga);
                int rb = wn * 32 + (lane & 7);
                int gbb = gb + ((lane >> 3) & 1);
#pragma unroll
                for (int nt = 0; nt < 4; nt++)
                    bAddr[nt] = ab + 16384 + SWM(rb + nt * 8, gbb);
            }
            uint32_t af[4][4], bh[4][2], bl[4][2];
#pragma unroll
            for (int mt = 0; mt < 4; mt++) ldm4(af[mt], aAddr[mt]);
#pragma unroll
            for (int nt = 0; nt < 4; nt++) ldm2(bh[nt], bAddr[nt]);
#pragma unroll
            for (int mt = 0; mt < 4; mt++)
#pragma unroll
                for (int nt = 0; nt < 4; nt++) mma16816(acc[mt][nt], af[mt], bh[nt]);
#pragma unroll
            for (int nt = 0; nt < 4; nt++) ldm2(bl[nt], bAddr[nt] + 8192);
#pragma unroll
            for (int mt = 0; mt < 4; mt++)
#pragma unroll
                for (int nt = 0; nt < 4; nt++) mma16816(acc[mt][nt], af[mt], bl[nt]);
#pragma unroll
            for (int mt = 0; mt < 4; mt++) ldm4(af[mt], aAddr[mt] + 8192);
#pragma unroll
            for (int mt = 0; mt < 4; mt++)
#pragma unroll
                for (int nt = 0; nt < 4; nt++) mma16816(acc[mt][nt], af[mt], bh[nt]);
        }
    }

    // ---- epilogue: bias, row-max, gumbel-argmax + sumexp partials ----
#pragma unroll
    for (int nt = 0; nt < 4; nt++) {
        int c0 = v0 + wn * 32 + nt * 8 + (lane & 3) * 2;
        float b0 = bout[c0], b1 = bout[c0 + 1];
#pragma unroll
        for (int mt = 0; mt < 4; mt++) {
            acc[mt][nt][0] += b0; acc[mt][nt][1] += b1;
            acc[mt][nt][2] += b0; acc[mt][nt][3] += b1;
        }
    }
    __syncthreads();
    float* msm = (float*)smem;          // [4][128]
    float* vsm = msm + 512;
    float* xsm = vsm + 512;
    float* ssm = xsm + 512;
    int*   ism = (int*)(ssm + 512);

    // pass1: per-CTA-row max
#pragma unroll
    for (int mt = 0; mt < 4; mt++) {
        float mA = -3.4e38f, mB = -3.4e38f;
#pragma unroll
        for (int nt = 0; nt < 4; nt++) {
            mA = fmaxf(mA, fmaxf(acc[mt][nt][0], acc[mt][nt][1]));
            mB = fmaxf(mB, fmaxf(acc[mt][nt][2], acc[mt][nt][3]));
        }
#pragma unroll
        for (int off = 1; off <= 2; off <<= 1) {
            mA = fmaxf(mA, __shfl_xor_sync(0xffffffffu, mA, off));
            mB = fmaxf(mB, __shfl_xor_sync(0xffffffffu, mB, off));
        }
        if ((lane & 3) == 0) {
            int r0 = wm * 64 + mt * 16 + (lane >> 2);
            msm[wn * 128 + r0] = mA;
            msm[wn * 128 + r0 + 8] = mB;
        }
    }
    __syncthreads();
    // pass2: argmax(logit+noise), sumexp
#pragma unroll
    for (int mt = 0; mt < 4; mt++) {
        int r0 = wm * 64 + mt * 16 + (lane >> 2), r1 = r0 + 8;
        float MA = fmaxf(fmaxf(msm[r0], msm[128 + r0]), fmaxf(msm[256 + r0], msm[384 + r0]));
        float MB = fmaxf(fmaxf(msm[r1], msm[128 + r1]), fmaxf(msm[256 + r1], msm[384 + r1]));
        int growA = rbase + r0, growB = rbase + r1;
        float sA = 0.0f, sB = 0.0f;
        float bvA = -3.4e38f, bvB = -3.4e38f, bxA = 0.0f, bxB = 0.0f;
        int biA = 0, biB = 0;
#pragma unroll
        for (int nt = 0; nt < 4; nt++) {
            int c0 = v0 + wn * 32 + nt * 8 + (lane & 3) * 2;
            float2 nA = *(const float2*)&g_noise[(size_t)growA * NV + c0];
            float2 nB = *(const float2*)&g_noise[(size_t)growB * NV + c0];
            float x0 = acc[mt][nt][0], x1 = acc[mt][nt][1];
            float vA0 = x0 + nA.x, vA1 = x1 + nA.y;
            if (vA0 > bvA) { bvA = vA0; biA = c0; bxA = x0; }
            if (vA1 > bvA) { bvA = vA1; biA = c0 + 1; bxA = x1; }
            sA += expf(x0 - MA) + expf(x1 - MA);
            float x2 = acc[mt][nt][2], x3 = acc[mt][nt][3];
            float vB0 = x2 + nB.x, vB1 = x3 + nB.y;
            if (vB0 > bvB) { bvB = vB0; biB = c0; bxB = x2; }
            if (vB1 > bvB) { bvB = vB1; biB = c0 + 1; bxB = x3; }
            sB += expf(x2 - MB) + expf(x3 - MB);
        }
#pragma unroll
        for (int off = 1; off <= 2; off <<= 1) {
            sA += __shfl_xor_sync(0xffffffffu, sA, off);
            sB += __shfl_xor_sync(0xffffffffu, sB, off);
            float ov = __shfl_xor_sync(0xffffffffu, bvA, off);
            int oi = __shfl_xor_sync(0xffffffffu, biA, off);
            float ox = __shfl_xor_sync(0xffffffffu, bxA, off);
            if (ov > bvA || (ov == bvA && oi < biA)) { bvA = ov; biA = oi; bxA = ox; }
            ov = __shfl_xor_sync(0xffffffffu, bvB, off);
            oi = __shfl_xor_sync(0xffffffffu, biB, off);
            ox = __shfl_xor_sync(0xffffffffu, bxB, off);
            if (ov > bvB || (ov == bvB && oi < biB)) { bvB = ov; biB = oi; bxB = ox; }
        }
        if ((lane & 3) == 0) {
            vsm[wn * 128 + r0] = bvA; ism[wn * 128 + r0] = biA;
            xsm[wn * 128 + r0] = bxA; ssm[wn * 128 + r0] = sA;
            vsm[wn * 128 + r1] = bvB; ism[wn * 128 + r1] = biB;
            xsm[wn * 128 + r1] = bxB; ssm[wn * 128 + r1] = sB;
        }
    }
    __syncthreads();
    if (tid < 128) {
        int r = tid, grow = rbase + r;
        float M = fmaxf(fmaxf(msm[r], msm[128 + r]), fmaxf(msm[256 + r], msm[384 + r]));
        float S = ssm[r] + ssm[128 + r] + ssm[256 + r] + ssm[384 + r];
        float bv = vsm[r]; int bi = ism[r]; float bx = xsm[r];
#pragma unroll
        for (int w = 1; w < 4; w++) {
            float ov = vsm[w * 128 + r]; int oi = ism[w * 128 + r];
            if (ov > bv || (ov == bv && oi < bi)) { bv = ov; bi = oi; bx = xsm[w * 128 + r]; }
        }
        g_partA[grow * 4 + blockIdx.x] = make_float4(bv, __int_as_float(bi), bx, M);
        g_partB[grow * 4 + blockIdx.x] = S;
    }
}

// ---------------- fin: combine step 15 + outputs ----------------
__global__ void fin_kernel(float* __restrict__ out) {
    int b = blockIdx.x * blockDim.x + threadIdx.x;
    if (b < NB) {
        float lp;
        int tok = combine_row(b, &lp);
        int alive = g_alive[1][b];   // alive after step 14 (written by k1 t=15)
        int tok_out = alive ? tok : 0;
        float logp = g_logp[b] + (alive ? lp : 0.0f);
        out[(size_t)b * NT + 15] = (float)tok_out;
        out[NB * NT + b] = (float)g_N[b];
        out[NB * NT + NB + b] = logp;
    }
}

extern "C" void kernel_launch(void* const* d_in, const int* in_sizes, int n_in,
                              void* d_out, int out_size) {
    const int* actions = (const int*)d_in[0];
    const float* h1 = (const float*)d_in[2];
    const float* d2e = (const float*)d_in[3];
    const float* Wih = (const float*)d_in[4];
    const float* Whh = (const float*)d_in[5];
    const float* bih = (const float*)d_in[6];
    const float* bhh = (const float*)d_in[7];
    const float* Wout = (const float*)d_in[8];
    const float* bout = (const float*)d_in[9];
    float* out = (float*)d_out;

    cudaFuncSetAttribute(k1_mma, cudaFuncAttributeMaxDynamicSharedMemorySize, K1_SMEM);
    cudaFuncSetAttribute(k2_mma, cudaFuncAttributeMaxDynamicSharedMemorySize, K2_SMEM);

    prep_kernel<<<1024, 256>>>(Wih, Whh, Wout);
    tgemm_kernel<<<64, 256>>>(d2e, bih, bhh);
    init_kernel<<<2048, 256>>>(actions, h1);
    for (int t = 0; t < NT; t++) {
        k1_mma<<<dim3(8, 128), 256, K1_SMEM>>>(t, bhh, out);
        k2_mma<<<dim3(4, 128), 256, K2_SMEM>>>((t & 1) ^ 1, bout);
    }
    fin_kernel<<<64, 256>>>(out);
}

// round 9
// speedup vs baseline: 2.5832x; 1.0059x over previous
#include <cuda_runtime.h>
#include <cuda_fp16.h>
#include <cstdint>

#define NB 16384
#define NE 256
#define NV 512
#define NT 16

// ---------------- scratch ----------------
__device__ __half g_st_h[2][NB * NE];
__device__ __half g_st_l[2][NB * NE];
__device__ __half g_GN_h[768 * 256];     // W_hh split (r,z,n stacked) [np][k]
__device__ __half g_GN_l[768 * 256];
__device__ __half g_Wo_h[NV * NE];
__device__ __half g_Wo_l[NV * NE];
__device__ float g_WihT[256 * 768];      // W_ih transposed [k][np]
__device__ float g_T[512 * 768];         // token gate table (fp32 exact)
__device__ float g_noiseAll[NT][NB * NV];   // per-step gumbel noise (side stream)
__device__ float4 g_partA[NB * 4];       // (bestval, idx-bits, x_best, M) per vblk
__device__ float g_partB[NB * 4];        // sumexp per vblk
__device__ int g_alive[2][NB];
__device__ int g_N[NB];
__device__ float g_logp[NB];
__device__ uint32_t g_keys[NT][2];

#define SWM(row, g) ((((row) * 4) + ((g) ^ ((((row) >> 1)) & 3))) * 16)
#define TINYF 1.17549435e-38f

__device__ __forceinline__ uint32_t smem_u32(const void* p) {
    uint32_t a;
    asm("{ .reg .u64 t; cvta.to.shared.u64 t, %1; cvt.u32.u64 %0, t; }" : "=r"(a) : "l"(p));
    return a;
}
__device__ __forceinline__ void cpa16(uint32_t s, const void* g) {
    asm volatile("cp.async.ca.shared.global [%0], [%1], 16;" :: "r"(s), "l"(g));
}
__device__ __forceinline__ void ldm4(uint32_t* r, uint32_t a) {
    asm volatile("ldmatrix.sync.aligned.m8n8.x4.shared.b16 {%0,%1,%2,%3}, [%4];"
                 : "=r"(r[0]), "=r"(r[1]), "=r"(r[2]), "=r"(r[3]) : "r"(a));
}
__device__ __forceinline__ void ldm2(uint32_t* r, uint32_t a) {
    asm volatile("ldmatrix.sync.aligned.m8n8.x2.shared.b16 {%0,%1}, [%2];"
                 : "=r"(r[0]), "=r"(r[1]) : "r"(a));
}
__device__ __forceinline__ void mma16816(float* c, const uint32_t* a, const uint32_t* b) {
    asm volatile(
        "mma.sync.aligned.m16n8k16.row.col.f32.f16.f16.f32 "
        "{%0,%1,%2,%3}, {%4,%5,%6,%7}, {%8,%9}, {%0,%1,%2,%3};"
        : "+f"(c[0]), "+f"(c[1]), "+f"(c[2]), "+f"(c[3])
        : "r"(a[0]), "r"(a[1]), "r"(a[2]), "r"(a[3]), "r"(b[0]), "r"(b[1]));
}
__device__ __forceinline__ void split2(float v, __half& h, __half& l) {
    h = __float2half(v);
    l = __float2half(v - __half2float(h));
}

// ---------------- threefry ----------------
__device__ __forceinline__ uint32_t rotl32(uint32_t v, int r) {
    return (v << r) | (v >> (32 - r));
}
__device__ __forceinline__ void tfry(uint32_t k0, uint32_t k1,
                                     uint32_t c0, uint32_t c1,
                                     uint32_t& o0, uint32_t& o1) {
    uint32_t k2 = k0 ^ k1 ^ 0x1BD11BDAu;
    uint32_t x0 = c0 + k0, x1 = c1 + k1;
#define R4(a,b,c,d) { x0+=x1; x1=rotl32(x1,a); x1^=x0; x0+=x1; x1=rotl32(x1,b); x1^=x0; \
                      x0+=x1; x1=rotl32(x1,c); x1^=x0; x0+=x1; x1=rotl32(x1,d); x1^=x0; }
    R4(13,15,26,6)  x0 += k1; x1 += k2 + 1u;
    R4(17,29,16,24) x0 += k2; x1 += k0 + 2u;
    R4(13,15,26,6)  x0 += k0; x1 += k1 + 3u;
    R4(17,29,16,24) x0 += k1; x1 += k2 + 4u;
    R4(13,15,26,6)  x0 += k2; x1 += k0 + 5u;
#undef R4
    o0 = x0; o1 = x1;
}

__device__ __forceinline__ int combine_row(int grow, float* lp_out) {
    float4 pa[4];
    float sv[4];
#pragma unroll
    for (int i = 0; i < 4; i++) {
        pa[i] = g_partA[grow * 4 + i];
        sv[i] = g_partB[grow * 4 + i];
    }
    float M = fmaxf(fmaxf(pa[0].w, pa[1].w), fmaxf(pa[2].w, pa[3].w));
    float S = 0.0f;
#pragma unroll
    for (int i = 0; i < 4; i++) S += sv[i] * expf(pa[i].w - M);
    float bv = pa[0].x;
    int bi = __float_as_int(pa[0].y);
    float bx = pa[0].z;
#pragma unroll
    for (int i = 1; i < 4; i++) {
        int oi = __float_as_int(pa[i].y);
        if (pa[i].x > bv || (pa[i].x == bv && oi < bi)) {
            bv = pa[i].x; bi = oi; bx = pa[i].z;
        }
    }
    *lp_out = bx - M - logf(S);
    return bi;
}

// ---------------- noise: gumbel for one step (side stream) ----------------
__global__ __launch_bounds__(256)
void noise_kernel(int t) {
    const uint32_t k0 = g_keys[t][0], k1 = g_keys[t][1];
    int i = blockIdx.x * blockDim.x + threadIdx.x;   // 0 .. NB*NV/4-1
    uint32_t base = (uint32_t)i * 4;
    float r[4];
#pragma unroll
    for (int q = 0; q < 4; q++) {
        uint32_t o0, o1;
        tfry(k0, k1, 0u, base + q, o0, o1);
        uint32_t bits = o0 ^ o1;
        float f = __uint_as_float((bits >> 9) | 0x3f800000u) - 1.0f;
        float u = fmaxf(TINYF, f * (1.0f - TINYF) + TINYF);
        r[q] = -logf(-logf(u));
    }
    *(float4*)&g_noiseAll[t][base] = make_float4(r[0], r[1], r[2], r[3]);
}

// ---------------- prep ----------------
__global__ void prep_kernel(const float* __restrict__ Wih,
                            const float* __restrict__ Whh,
                            const float* __restrict__ Wout) {
    int tid = blockIdx.x * blockDim.x + threadIdx.x;
    int stride = gridDim.x * blockDim.x;
    for (int i = tid; i < 768 * 256; i += stride) {
        __half h, l; split2(Whh[i], h, l);
        g_GN_h[i] = h; g_GN_l[i] = l;
    }
    for (int i = tid; i < 256 * 768; i += stride) {
        int k = i / 768, np = i - k * 768;
        g_WihT[i] = Wih[np * 256 + k];
    }
    for (int i = tid; i < NV * NE; i += stride) {
        __half h, l;
        split2(Wout[i], h, l);
        g_Wo_h[i] = h; g_Wo_l[i] = l;
    }
    if (blockIdx.x == 0 && threadIdx.x == 0) {
        for (int t = 0; t < NT; t++) {
            uint32_t a, b;
            tfry(0u, 42u, 0u, (uint32_t)t, a, b);
            g_keys[t][0] = a; g_keys[t][1] = b;
        }
    }
}

// T[tok][np] = d2e[tok] . Wih[np] + bih[np] + (np<512 ? bhh[np] : 0)
__global__ __launch_bounds__(256)
void tgemm_kernel(const float* __restrict__ d2e,
                  const float* __restrict__ bih,
                  const float* __restrict__ bhh) {
    __shared__ float es[8][256];
    int tokbase = blockIdx.x * 8;
    int tid = threadIdx.x;
    for (int i = tid; i < 8 * 256; i += 256)
        es[i >> 8][i & 255] = d2e[(tokbase + (i >> 8)) * 256 + (i & 255)];
    __syncthreads();
#pragma unroll
    for (int p = 0; p < 3; p++) {
        int np = tid + p * 256;
        float acc[8];
        float bias = bih[np] + (np < 512 ? bhh[np] : 0.0f);
#pragma unroll
        for (int t = 0; t < 8; t++) acc[t] = 0.0f;
        for (int k = 0; k < 256; k++) {
            float w = g_WihT[k * 768 + np];
#pragma unroll
            for (int t = 0; t < 8; t++) acc[t] += es[t][k] * w;
        }
#pragma unroll
        for (int t = 0; t < 8; t++)
            g_T[(tokbase + t) * 768 + np] = acc[t] + bias;
    }
}

__global__ void init_kernel(const int* __restrict__ actions,
                            const float* __restrict__ h1) {
    int tid = blockIdx.x * blockDim.x + threadIdx.x;
    int stride = gridDim.x * blockDim.x;
    for (int i = tid; i < NB * NE; i += stride) {
        int b = i >> 8, e = i & 255;
        float v = h1[actions[b] * NE + e];
        __half h, l; split2(v, h, l);
        g_st_h[0][i] = h; g_st_l[0][i] = l;
    }
    for (int i = tid; i < NB; i += stride) {
        g_alive[0][i] = 1; g_N[i] = NT; g_logp[i] = 0.0f;
    }
}

// ============ K1: combine(t-1) + state @ Whh^T + GRU epilogue ============
#define K1_STAGE 28672
#define K1_SMEM (3 * K1_STAGE + 512)
__global__ __launch_bounds__(256, 2)
void k1_mma(int t, const float* __restrict__ bhh, float* __restrict__ out) {
    extern __shared__ char smem[];
    const uint32_t sbase = smem_u32(smem);
    const int tid = threadIdx.x;
    const int lane = tid & 31, wid = tid >> 5;
    const int wm = wid & 3, wn = wid >> 2;
    const int j0 = blockIdx.x * 32;
    const int rbase = blockIdx.y * 128;
    const int cur = t & 1, nxt = cur ^ 1;
    int* tok_sm = (int*)(smem + 3 * K1_STAGE);

    const int arow = tid >> 1, ahalf = tid & 1;
    const uint32_t sw0 = SWM(arow, ahalf * 2);
    const uint32_t sw1 = SWM(arow, ahalf * 2 + 1);
    const size_t aoff = (size_t)(rbase + arow) * 256 + ahalf * 16;

    float acc[2][6][4];
#pragma unroll
    for (int i = 0; i < 2; i++)
#pragma unroll
        for (int j = 0; j < 6; j++)
#pragma unroll
            for (int q = 0; q < 4; q++) acc[i][j][q] = 0.0f;

    int b_half[3];
    size_t b_src[3];
    uint32_t b_dst[3];
#pragma unroll
    for (int i = 0; i < 3; i++) {
        int o = tid + 256 * i;
        int half = o >= 384;
        int rem = o - half * 384;
        int brow = rem >> 2, grp = rem & 3;
        b_half[i] = half;
        int grow = (brow >> 5) * 256 + j0 + (brow & 31);
        b_src[i] = (size_t)grow * 256 + grp * 8;
        b_dst[i] = 16384 + half * 6144 + SWM(brow, grp);
    }

    auto stage = [&](int c, int buf) {
        uint32_t ab = sbase + buf * K1_STAGE;
        size_t off = aoff + c * 32;
        cpa16(ab + sw0, g_st_h[cur] + off);
        cpa16(ab + sw1, g_st_h[cur] + off + 8);
        cpa16(ab + 8192 + sw0, g_st_l[cur] + off);
        cpa16(ab + 8192 + sw1, g_st_l[cur] + off + 8);
#pragma unroll
        for (int i = 0; i < 3; i++) {
            const __half* src = (b_half[i] ? g_GN_l : g_GN_h) + b_src[i] + c * 32;
            cpa16(ab + b_dst[i], src);
        }
    };

    stage(0, 0);
    asm volatile("cp.async.commit_group;");
    stage(1, 1);
    asm volatile("cp.async.commit_group;");

    // ---- prologue: combine step t-1 partials -> token (+ bookkeeping on jblk0)
    if (tid < 128) {
        int grow = rbase + tid;
        int tok_out = 0;
        if (t > 0) {
            float lp;
            int tok = combine_row(grow, &lp);
            int alive = g_alive[(t - 1) & 1][grow];
            tok_out = alive ? tok : 0;
            if (blockIdx.x == 0) {
                if (alive) g_logp[grow] += lp;
                if (alive && tok == 0) g_N[grow] = t;
                g_alive[t & 1][grow] = (alive && tok != 0) ? 1 : 0;
                out[(size_t)grow * NT + (t - 1)] = (float)tok_out;
            }
        }
        tok_sm[tid] = tok_out;
    }

    for (int c = 0; c < 8; c++) {
        if (c < 7) asm volatile("cp.async.wait_group 1;");
        else       asm volatile("cp.async.wait_group 0;");
        __syncthreads();
        if (c < 6) {
            stage(c + 2, (c + 2) % 3);
            asm volatile("cp.async.commit_group;");
        }
        uint32_t ab = sbase + (c % 3) * K1_STAGE;
#pragma unroll
        for (int q = 0; q < 2; q++) {
            int gb = q * 2;
            uint32_t aAddr[2], bAddr[6];
            {
                int rl = wm * 32 + (lane & 15);
                int ga = gb + (lane >> 4);
#pragma unroll
                for (int mt = 0; mt < 2; mt++)
                    aAddr[mt] = ab + SWM(rl + mt * 16, ga);
                int rb0 = wn * 48 + (lane & 7);
                int gbb = gb + ((lane >> 3) & 1);
#pragma unroll
                for (int nt = 0; nt < 6; nt++)
                    bAddr[nt] = ab + 16384 + SWM(rb0 + nt * 8, gbb);
            }
            uint32_t af[2][4], bh[6][2], bl[6][2];
#pragma unroll
            for (int mt = 0; mt < 2; mt++) ldm4(af[mt], aAddr[mt]);
#pragma unroll
            for (int nt = 0; nt < 6; nt++) ldm2(bh[nt], bAddr[nt]);
#pragma unroll
            for (int mt = 0; mt < 2; mt++)
#pragma unroll
                for (int nt = 0; nt < 6; nt++) mma16816(acc[mt][nt], af[mt], bh[nt]);
#pragma unroll
            for (int nt = 0; nt < 6; nt++) ldm2(bl[nt], bAddr[nt] + 6144);
#pragma unroll
            for (int mt = 0; mt < 2; mt++)
#pragma unroll
                for (int nt = 0; nt < 6; nt++) mma16816(acc[mt][nt], af[mt], bl[nt]);
#pragma unroll
            for (int mt = 0; mt < 2; mt++) ldm4(af[mt], aAddr[mt] + 8192);
#pragma unroll
            for (int mt = 0; mt < 2; mt++)
#pragma unroll
                for (int nt = 0; nt < 6; nt++) mma16816(acc[mt][nt], af[mt], bh[nt]);
        }
    }

    // ---- epilogue: dump C, token-table GRU, split-store state ----
    float* Cs = (float*)smem;
    __syncthreads();
#pragma unroll
    for (int mt = 0; mt < 2; mt++)
#pragma unroll
        for (int nt = 0; nt < 6; nt++) {
            int r0 = wm * 32 + mt * 16 + (lane >> 2);
            int c0 = wn * 48 + nt * 8 + (lane & 3) * 2;
            Cs[r0 * 100 + c0] = acc[mt][nt][0];
            Cs[r0 * 100 + c0 + 1] = acc[mt][nt][1];
            Cs[(r0 + 8) * 100 + c0] = acc[mt][nt][2];
            Cs[(r0 + 8) * 100 + c0 + 1] = acc[mt][nt][3];
        }
    __syncthreads();
    {
        int jl = tid & 31, rseg = tid >> 5;
        int j = j0 + jl;
        float bhn = bhh[512 + j];
#pragma unroll
        for (int rr = 0; rr < 16; rr++) {
            int r = rseg * 16 + rr;
            int grow = rbase + r;
            int tok = tok_sm[r];
            const float* Trow = g_T + (size_t)tok * 768;
            float cr = Cs[r * 100 + jl] + Trow[j];
            float cz = Cs[r * 100 + 32 + jl] + Trow[256 + j];
            float cn = Cs[r * 100 + 64 + jl] + bhn;
            size_t so = (size_t)grow * 256 + j;
            float hold = __half2float(g_st_h[cur][so]) + __half2float(g_st_l[cur][so]);
            float rg = 1.0f / (1.0f + expf(-cr));
            float zg = 1.0f / (1.0f + expf(-cz));
            float nn = tanhf(Trow[512 + j] + rg * cn);
            float v = (1.0f - zg) * nn + zg * hold;
            __half hh, hl;
            split2(v, hh, hl);
            g_st_h[nxt][so] = hh;
            g_st_l[nxt][so] = hl;
        }
    }
}

// ============ K2: logits GEMM + fused gumbel-argmax partials ============
#define K2_SMEM (3 * 32768)
__global__ __launch_bounds__(256, 2)
void k2_mma(int t, const float* __restrict__ bout) {
    extern __shared__ char smem[];
    const uint32_t sbase = smem_u32(smem);
    const int tid = threadIdx.x;
    const int lane = tid & 31, wid = tid >> 5;
    const int wm = wid & 1, wn = wid >> 1;
    const int v0 = blockIdx.x * 128;
    const int rbase = blockIdx.y * 128;
    const int nxt = (t + 1) & 1;
    const float* __restrict__ noise = g_noiseAll[t];

    const int arow = tid >> 1, ahalf = tid & 1;
    const uint32_t sw0 = SWM(arow, ahalf * 2);
    const uint32_t sw1 = SWM(arow, ahalf * 2 + 1);

    float acc[4][4][4];
#pragma unroll
    for (int i = 0; i < 4; i++)
#pragma unroll
        for (int j = 0; j < 4; j++)
#pragma unroll
            for (int q = 0; q < 4; q++) acc[i][j][q] = 0.0f;

    auto stage = [&](int c, int buf) {
        uint32_t ab = sbase + buf * 32768;
        size_t off = (size_t)(rbase + arow) * 256 + c * 32 + ahalf * 16;
        cpa16(ab + sw0, g_st_h[nxt] + off);
        cpa16(ab + sw1, g_st_h[nxt] + off + 8);
        cpa16(ab + 8192 + sw0, g_st_l[nxt] + off);
        cpa16(ab + 8192 + sw1, g_st_l[nxt] + off + 8);
        size_t offb = (size_t)(v0 + arow) * 256 + c * 32 + ahalf * 16;
        cpa16(ab + 16384 + sw0, g_Wo_h + offb);
        cpa16(ab + 16384 + sw1, g_Wo_h + offb + 8);
        cpa16(ab + 24576 + sw0, g_Wo_l + offb);
        cpa16(ab + 24576 + sw1, g_Wo_l + offb + 8);
    };

    stage(0, 0);
    asm volatile("cp.async.commit_group;");
    stage(1, 1);
    asm volatile("cp.async.commit_group;");

    for (int c = 0; c < 8; c++) {
        if (c < 7) asm volatile("cp.async.wait_group 1;");
        else       asm volatile("cp.async.wait_group 0;");
        __syncthreads();
        if (c < 6) {
            stage(c + 2, (c + 2) % 3);
            asm volatile("cp.async.commit_group;");
        }
        uint32_t ab = sbase + (c % 3) * 32768;
#pragma unroll
        for (int q = 0; q < 2; q++) {
            int gb = q * 2;
            uint32_t aAddr[4], bAddr[4];
            {
                int rl = wm * 64 + (lane & 15);
                int ga = gb + (lane >> 4);
#pragma unroll
                for (int mt = 0; mt < 4; mt++)
                    aAddr[mt] = ab + SWM(rl + mt * 16, ga);
                int rb = wn * 32 + (lane & 7);
                int gbb = gb + ((lane >> 3) & 1);
#pragma unroll
                for (int nt = 0; nt < 4; nt++)
                    bAddr[nt] = ab + 16384 + SWM(rb + nt * 8, gbb);
            }
            uint32_t af[4][4], bh[4][2], bl[4][2];
#pragma unroll
            for (int mt = 0; mt < 4; mt++) ldm4(af[mt], aAddr[mt]);
#pragma unroll
            for (int nt = 0; nt < 4; nt++) ldm2(bh[nt], bAddr[nt]);
#pragma unroll
            for (int mt = 0; mt < 4; mt++)
#pragma unroll
                for (int nt = 0; nt < 4; nt++) mma16816(acc[mt][nt], af[mt], bh[nt]);
#pragma unroll
            for (int nt = 0; nt < 4; nt++) ldm2(bl[nt], bAddr[nt] + 8192);
#pragma unroll
            for (int mt = 0; mt < 4; mt++)
#pragma unroll
                for (int nt = 0; nt < 4; nt++) mma16816(acc[mt][nt], af[mt], bl[nt]);
#pragma unroll
            for (int mt = 0; mt < 4; mt++) ldm4(af[mt], aAddr[mt] + 8192);
#pragma unroll
            for (int mt = 0; mt < 4; mt++)
#pragma unroll
                for (int nt = 0; nt < 4; nt++) mma16816(acc[mt][nt], af[mt], bh[nt]);
        }
    }

    // ---- epilogue: bias, row-max, gumbel-argmax + sumexp partials ----
#pragma unroll
    for (int nt = 0; nt < 4; nt++) {
        int c0 = v0 + wn * 32 + nt * 8 + (lane & 3) * 2;
        float b0 = bout[c0], b1 = bout[c0 + 1];
#pragma unroll
        for (int mt = 0; mt < 4; mt++) {
            acc[mt][nt][0] += b0; acc[mt][nt][1] += b1;
            acc[mt][nt][2] += b0; acc[mt][nt][3] += b1;
        }
    }
    __syncthreads();
    float* msm = (float*)smem;          // [4][128]
    float* vsm = msm + 512;
    float* xsm = vsm + 512;
    float* ssm = xsm + 512;
    int*   ism = (int*)(ssm + 512);

#pragma unroll
    for (int mt = 0; mt < 4; mt++) {
        float mA = -3.4e38f, mB = -3.4e38f;
#pragma unroll
        for (int nt = 0; nt < 4; nt++) {
            mA = fmaxf(mA, fmaxf(acc[mt][nt][0], acc[mt][nt][1]));
            mB = fmaxf(mB, fmaxf(acc[mt][nt][2], acc[mt][nt][3]));
        }
#pragma unroll
        for (int off = 1; off <= 2; off <<= 1) {
            mA = fmaxf(mA, __shfl_xor_sync(0xffffffffu, mA, off));
            mB = fmaxf(mB, __shfl_xor_sync(0xffffffffu, mB, off));
        }
        if ((lane & 3) == 0) {
            int r0 = wm * 64 + mt * 16 + (lane >> 2);
            msm[wn * 128 + r0] = mA;
            msm[wn * 128 + r0 + 8] = mB;
        }
    }
    __syncthreads();
#pragma unroll
    for (int mt = 0; mt < 4; mt++) {
        int r0 = wm * 64 + mt * 16 + (lane >> 2), r1 = r0 + 8;
        float MA = fmaxf(fmaxf(msm[r0], msm[128 + r0]), fmaxf(msm[256 + r0], msm[384 + r0]));
        float MB = fmaxf(fmaxf(msm[r1], msm[128 + r1]), fmaxf(msm[256 + r1], msm[384 + r1]));
        int growA = rbase + r0, growB = rbase + r1;
        float sA = 0.0f, sB = 0.0f;
        float bvA = -3.4e38f, bvB = -3.4e38f, bxA = 0.0f, bxB = 0.0f;
        int biA = 0, biB = 0;
#pragma unroll
        for (int nt = 0; nt < 4; nt++) {
            int c0 = v0 + wn * 32 + nt * 8 + (lane & 3) * 2;
            float2 nA = *(const float2*)&noise[(size_t)growA * NV + c0];
            float2 nB = *(const float2*)&noise[(size_t)growB * NV + c0];
            float x0 = acc[mt][nt][0], x1 = acc[mt][nt][1];
            float vA0 = x0 + nA.x, vA1 = x1 + nA.y;
            if (vA0 > bvA) { bvA = vA0; biA = c0; bxA = x0; }
            if (vA1 > bvA) { bvA = vA1; biA = c0 + 1; bxA = x1; }
            sA += expf(x0 - MA) + expf(x1 - MA);
            float x2 = acc[mt][nt][2], x3 = acc[mt][nt][3];
            float vB0 = x2 + nB.x, vB1 = x3 + nB.y;
            if (vB0 > bvB) { bvB = vB0; biB = c0; bxB = x2; }
            if (vB1 > bvB) { bvB = vB1; biB = c0 + 1; bxB = x3; }
            sB += expf(x2 - MB) + expf(x3 - MB);
        }
#pragma unroll
        for (int off = 1; off <= 2; off <<= 1) {
            sA += __shfl_xor_sync(0xffffffffu, sA, off);
            sB += __shfl_xor_sync(0xffffffffu, sB, off);
            float ov = __shfl_xor_sync(0xffffffffu, bvA, off);
            int oi = __shfl_xor_sync(0xffffffffu, biA, off);
            float ox = __shfl_xor_sync(0xffffffffu, bxA, off);
            if (ov > bvA || (ov == bvA && oi < biA)) { bvA = ov; biA = oi; bxA = ox; }
            ov = __shfl_xor_sync(0xffffffffu, bvB, off);
            oi = __shfl_xor_sync(0xffffffffu, biB, off);
            ox = __shfl_xor_sync(0xffffffffu, bxB, off);
            if (ov > bvB || (ov == bvB && oi < biB)) { bvB = ov; biB = oi; bxB = ox; }
        }
        if ((lane & 3) == 0) {
            vsm[wn * 128 + r0] = bvA; ism[wn * 128 + r0] = biA;
            xsm[wn * 128 + r0] = bxA; ssm[wn * 128 + r0] = sA;
            vsm[wn * 128 + r1] = bvB; ism[wn * 128 + r1] = biB;
            xsm[wn * 128 + r1] = bxB; ssm[wn * 128 + r1] = sB;
        }
    }
    __syncthreads();
    if (tid < 128) {
        int r = tid, grow = rbase + r;
        float M = fmaxf(fmaxf(msm[r], msm[128 + r]), fmaxf(msm[256 + r], msm[384 + r]));
        float S = ssm[r] + ssm[128 + r] + ssm[256 + r] + ssm[384 + r];
        float bv = vsm[r]; int bi = ism[r]; float bx = xsm[r];
#pragma unroll
        for (int w = 1; w < 4; w++) {
            float ov = vsm[w * 128 + r]; int oi = ism[w * 128 + r];
            if (ov > bv || (ov == bv && oi < bi)) { bv = ov; bi = oi; bx = xsm[w * 128 + r]; }
        }
        g_partA[grow * 4 + blockIdx.x] = make_float4(bv, __int_as_float(bi), bx, M);
        g_partB[grow * 4 + blockIdx.x] = S;
    }
}

// ---------------- fin: combine step 15 + outputs ----------------
__global__ void fin_kernel(float* __restrict__ out) {
    int b = blockIdx.x * blockDim.x + threadIdx.x;
    if (b < NB) {
        float lp;
        int tok = combine_row(b, &lp);
        int alive = g_alive[1][b];
        int tok_out = alive ? tok : 0;
        float logp = g_logp[b] + (alive ? lp : 0.0f);
        out[(size_t)b * NT + 15] = (float)tok_out;
        out[NB * NT + b] = (float)g_N[b];
        out[NB * NT + NB + b] = logp;
    }
}

extern "C" void kernel_launch(void* const* d_in, const int* in_sizes, int n_in,
                              void* d_out, int out_size) {
    const int* actions = (const int*)d_in[0];
    const float* h1 = (const float*)d_in[2];
    const float* d2e = (const float*)d_in[3];
    const float* Wih = (const float*)d_in[4];
    const float* Whh = (const float*)d_in[5];
    const float* bih = (const float*)d_in[6];
    const float* bhh = (const float*)d_in[7];
    const float* Wout = (const float*)d_in[8];
    const float* bout = (const float*)d_in[9];
    float* out = (float*)d_out;

    // one-time resource init (host-side only; no device allocations)
    static cudaStream_t s_side = nullptr;
    static cudaEvent_t s_evRoot = nullptr;
    static cudaEvent_t s_evN[NT];
    if (!s_side) {
        int loPrio = 0, hiPrio = 0;
        cudaDeviceGetStreamPriorityRange(&loPrio, &hiPrio);
        cudaStreamCreateWithPriority(&s_side, cudaStreamNonBlocking, loPrio);
        cudaEventCreateWithFlags(&s_evRoot, cudaEventDisableTiming);
        for (int t = 0; t < NT; t++)
            cudaEventCreateWithFlags(&s_evN[t], cudaEventDisableTiming);
        cudaFuncSetAttribute(k1_mma, cudaFuncAttributeMaxDynamicSharedMemorySize, K1_SMEM);
        cudaFuncSetAttribute(k2_mma, cudaFuncAttributeMaxDynamicSharedMemorySize, K2_SMEM);
    }

    prep_kernel<<<1024, 256>>>(Wih, Whh, Wout);
    tgemm_kernel<<<64, 256>>>(d2e, bih, bhh);
    init_kernel<<<2048, 256>>>(actions, h1);

    // fork: low-priority side stream computes all 16 steps of gumbel noise
    cudaEventRecord(s_evRoot, 0);
    cudaStreamWaitEvent(s_side, s_evRoot, 0);
    for (int t = 0; t < NT; t++) {
        noise_kernel<<<NB * NV / 4 / 256, 256, 0, s_side>>>(t);
        cudaEventRecord(s_evN[t], s_side);
    }

    for (int t = 0; t < NT; t++) {
        k1_mma<<<dim3(8, 128), 256, K1_SMEM>>>(t, bhh, out);
        cudaStreamWaitEvent(0, s_evN[t], 0);   // join: noise(t) ready before K2(t)
        k2_mma<<<dim3(4, 128), 256, K2_SMEM>>>(t, bout);
    }
    fin_kernel<<<64, 256>>>(out);
}